// round 8
// baseline (speedup 1.0000x reference)
#include <cuda_runtime.h>
#include <math.h>
#include <stdint.h>

#define B_ 8
#define C_ 384
#define HW_ 4096

// Scratch (device globals — no runtime allocation)
__device__ float g_buf0[B_ * C_ * HW_];   // xdw, later xi
__device__ float g_buf1[B_ * C_ * HW_];   // xs,  later y
__device__ float g_z[B_ * HW_ * C_];      // z token-major
__device__ float g_gate[C_ * HW_];        // spectral gate [c][n*64+k]
__device__ float g_W[64 * 64];            // DCT-II basis (Wh == Ww)

// ---------------------------------------------------------------------------
// helpers: tf32 conversion + m16n8k8 tf32 mma
// ---------------------------------------------------------------------------
__device__ __forceinline__ uint32_t f2tf(float f) {
    uint32_t u;
    asm("cvt.rna.tf32.f32 %0, %1;" : "=r"(u) : "f"(f));
    return u;
}

__device__ __forceinline__ void mma8(float* c, uint32_t a0, uint32_t a1,
                                     uint32_t a2, uint32_t a3,
                                     uint32_t b0, uint32_t b1) {
    asm volatile(
        "mma.sync.aligned.m16n8k8.row.col.f32.tf32.tf32.f32 "
        "{%0,%1,%2,%3}, {%4,%5,%6,%7}, {%8,%9}, {%0,%1,%2,%3};"
        : "+f"(c[0]), "+f"(c[1]), "+f"(c[2]), "+f"(c[3])
        : "r"(a0), "r"(a1), "r"(a2), "r"(a3), "r"(b0), "r"(b1));
}

// ---------------------------------------------------------------------------
// DCT basis
// ---------------------------------------------------------------------------
__global__ void k_dct_basis() {
    int n = blockIdx.x, x = threadIdx.x;
    float v = cosf((float)n * ((float)x + 0.5f) * (3.14159265358979323846f / 64.0f))
              * 0.17677669529663687f;
    if (n == 0) v *= 0.70710678118654752f;
    g_W[n * 64 + x] = v;
}

// ---------------------------------------------------------------------------
// Depthwise 3x3 conv (SAME) + bias. One block per (b,c) image.
// ---------------------------------------------------------------------------
__global__ void k_dwconv(const float* __restrict__ x,
                         const float* __restrict__ w,
                         const float* __restrict__ bias) {
    __shared__ float s[66 * 68];
    int bc = blockIdx.x;
    const float* xim = x + (size_t)bc * HW_;
    int tid = threadIdx.x;
    for (int i = tid; i < 66 * 66; i += 256) {
        int r = i / 66, cl = i % 66;
        int gh = r - 1, gw = cl - 1;
        float v = 0.0f;
        if ((unsigned)gh < 64u && (unsigned)gw < 64u) v = xim[gh * 64 + gw];
        s[r * 68 + cl] = v;
    }
    int c = bc % C_;
    const float* wp = w + c * 9;
    float w0 = wp[0], w1 = wp[1], w2 = wp[2];
    float w3 = wp[3], w4 = wp[4], w5 = wp[5];
    float w6 = wp[6], w7 = wp[7], w8 = wp[8];
    float bv = bias[c];
    __syncthreads();
    float* outp = g_buf0 + (size_t)bc * HW_;
    for (int p = tid; p < HW_; p += 256) {
        int h = p >> 6, ww = p & 63;
        const float* sp = s + h * 68 + ww;
        float acc = bv;
        acc = fmaf(sp[0],   w0, acc); acc = fmaf(sp[1],   w1, acc); acc = fmaf(sp[2],   w2, acc);
        acc = fmaf(sp[68],  w3, acc); acc = fmaf(sp[69],  w4, acc); acc = fmaf(sp[70],  w5, acc);
        acc = fmaf(sp[136], w6, acc); acc = fmaf(sp[137], w7, acc); acc = fmaf(sp[138], w8, acc);
        outp[p] = acc;
    }
}

// ===========================================================================
// GEMM core v3: block 128(M) x 128(N), 256 threads = 8 warps (2m x 4n),
// warp tile 64x32 (4 m-frags x 4 n-frags). K chunks of 32, 12 chunks.
// Software-pipelined: double-buffered smem + register prefetch of chunk k+1
// issued before the mma block on chunk k. One __syncthreads per chunk.
// Per-element K accumulation order identical to v2 -> bit-identical numerics.
// smem: 2 x (sA[128][36] + sB[128][36]) tf32 = 73728 B (dynamic).
// AMODE 0: A gmem [K][M] (m contiguous); AMODE 1: A gmem [M][K].
// B gmem [N][K], k contiguous (ld = 384).
// ---------------------------------------------------------------------------
#define GEMM_SMEM_BYTES (4 * 128 * 36 * 4)   // 73728
#define BUFW (2 * 128 * 36)                  // words per buffer (sA+sB)

template<int AMODE>
__device__ __forceinline__ void gemm_core(const float* __restrict__ Ag, int lda,
                                          const float* __restrict__ Bg,
                                          int m0, int n0, int tid,
                                          uint32_t* sm, float acc[4][4][4]) {
    int lane = tid & 31, g = lane >> 2, t4 = lane & 3;
    int warp = tid >> 5, wm = warp & 1, wn = warp >> 1;

    float4 ra[4], rb[4];

    // gmem -> regs for chunk starting at kt
    auto load_regs = [&](int kt) {
        if (AMODE == 0) {
            #pragma unroll
            for (int j = 0; j < 4; j++) {
                int mm = tid & 127, k4 = (tid >> 7) + 2 * j;
                const float* p = Ag + (size_t)(kt + 4 * k4) * lda + m0 + mm;
                ra[j] = make_float4(p[0], p[lda], p[2 * lda], p[3 * lda]);
            }
        } else {
            #pragma unroll
            for (int j = 0; j < 4; j++) {
                int k4 = tid & 7, mm = (tid >> 3) + 32 * j;
                ra[j] = *(const float4*)(Ag + (size_t)(m0 + mm) * lda + kt + 4 * k4);
            }
        }
        #pragma unroll
        for (int j = 0; j < 4; j++) {
            int k4 = tid & 7, nn = (tid >> 3) + 32 * j;
            rb[j] = *(const float4*)(Bg + (size_t)(n0 + nn) * C_ + kt + 4 * k4);
        }
    };

    // regs -> smem buffer
    auto store_smem = [&](uint32_t* buf) {
        uint32_t* sA = buf;
        uint32_t* sB = buf + 128 * 36;
        #pragma unroll
        for (int j = 0; j < 4; j++) {
            uint4 v;
            v.x = f2tf(ra[j].x); v.y = f2tf(ra[j].y);
            v.z = f2tf(ra[j].z); v.w = f2tf(ra[j].w);
            if (AMODE == 0) {
                int mm = tid & 127, k4 = (tid >> 7) + 2 * j;
                *(uint4*)(sA + mm * 36 + 4 * k4) = v;
            } else {
                int k4 = tid & 7, mm = (tid >> 3) + 32 * j;
                *(uint4*)(sA + mm * 36 + 4 * k4) = v;
            }
        }
        #pragma unroll
        for (int j = 0; j < 4; j++) {
            int k4 = tid & 7, nn = (tid >> 3) + 32 * j;
            uint4 v;
            v.x = f2tf(rb[j].x); v.y = f2tf(rb[j].y);
            v.z = f2tf(rb[j].z); v.w = f2tf(rb[j].w);
            *(uint4*)(sB + nn * 36 + 4 * k4) = v;
        }
    };

    load_regs(0);
    store_smem(sm);
    __syncthreads();

    #pragma unroll 1
    for (int kc = 0; kc < 12; kc++) {
        int cur = kc & 1;
        if (kc + 1 < 12) load_regs((kc + 1) * 32);   // prefetch next chunk

        uint32_t* sA = sm + cur * BUFW;
        uint32_t* sB = sA + 128 * 36;
        #pragma unroll
        for (int k8 = 0; k8 < 4; k8++) {
            uint32_t a[4][4], bq[4][2];
            #pragma unroll
            for (int mf = 0; mf < 4; mf++) {
                const uint32_t* pa = sA + (wm * 64 + mf * 16 + g) * 36 + k8 * 8 + t4;
                a[mf][0] = pa[0];
                a[mf][1] = pa[8 * 36];
                a[mf][2] = pa[4];
                a[mf][3] = pa[8 * 36 + 4];
            }
            #pragma unroll
            for (int nf = 0; nf < 4; nf++) {
                const uint32_t* pb = sB + (wn * 32 + nf * 8 + g) * 36 + k8 * 8 + t4;
                bq[nf][0] = pb[0];
                bq[nf][1] = pb[4];
            }
            #pragma unroll
            for (int mf = 0; mf < 4; mf++)
                #pragma unroll
                for (int nf = 0; nf < 4; nf++)
                    mma8(acc[mf][nf], a[mf][0], a[mf][1], a[mf][2], a[mf][3],
                         bq[nf][0], bq[nf][1]);
        }
        if (kc + 1 < 12) {
            store_smem(sm + (cur ^ 1) * BUFW);
            __syncthreads();
        }
    }
}

// Chunked NCHW epilogue: 4 chunks of 32 channels (chunk c by warps wn==c),
// staged [ch][m] stride 132 (conflict-free).
template<typename F>
__device__ __forceinline__ void epi_nchw(uint32_t* sm, float acc[4][4][4],
                                         int tid, float* dst, int strideM,
                                         int m0, int n0, F f) {
    float* sC = (float*)sm;
    int lane = tid & 31, g = lane >> 2, t4 = lane & 3;
    int warp = tid >> 5, wm = warp & 1, wn = warp >> 1;
    __syncthreads();
    #pragma unroll
    for (int c = 0; c < 4; c++) {
        if (wn == c) {
            #pragma unroll
            for (int mf = 0; mf < 4; mf++) {
                int r = wm * 64 + mf * 16 + g;
                #pragma unroll
                for (int nf = 0; nf < 4; nf++) {
                    int chl = nf * 8 + 2 * t4;
                    sC[chl * 132 + r]           = acc[mf][nf][0];
                    sC[(chl + 1) * 132 + r]     = acc[mf][nf][1];
                    sC[chl * 132 + r + 8]       = acc[mf][nf][2];
                    sC[(chl + 1) * 132 + r + 8] = acc[mf][nf][3];
                }
            }
        }
        __syncthreads();
        for (int i = tid; i < 4096; i += 256) {
            int ch = i >> 7, mm = i & 127;
            int gc = n0 + 32 * c + ch;
            dst[(size_t)gc * strideM + m0 + mm] = f(sC[ch * 132 + mm], gc);
        }
        __syncthreads();
    }
}

// ---------------------------------------------------------------------------
// lin GEMM: xz[m][d] = sum_c xdw[c][m]*lin_w[d][c] + lin_b[d]
// by 0..2 -> xs (NCHW); by 3..5 -> z (token-major)
// ---------------------------------------------------------------------------
struct AddBias {
    const float* b;
    __device__ float operator()(float v, int ch) const { return v + b[ch]; }
};

__global__ void __launch_bounds__(256, 2) k_lin_mma(const float* __restrict__ lw,
                                                    const float* __restrict__ lb) {
    extern __shared__ __align__(16) uint32_t sm[];
    int tid = threadIdx.x;
    int b = blockIdx.z, m0 = blockIdx.x * 128, n0 = blockIdx.y * 128;
    float acc[4][4][4];
    #pragma unroll
    for (int i = 0; i < 4; i++)
        #pragma unroll
        for (int j = 0; j < 4; j++)
            #pragma unroll
            for (int k = 0; k < 4; k++) acc[i][j][k] = 0.0f;

    gemm_core<0>(g_buf0 + (size_t)b * C_ * HW_, HW_, lw, m0, n0, tid, sm, acc);

    if (n0 < C_) {
        epi_nchw(sm, acc, tid, g_buf1 + (size_t)b * C_ * HW_, HW_, m0, n0,
                 AddBias{lb});
    } else {
        // z half -> token-major [m][C_], 2 chunks of 64 rows (by wm)
        float* sC = (float*)sm;
        int lane = tid & 31, g = lane >> 2, t4 = lane & 3;
        int warp = tid >> 5, wm = warp & 1, wn = warp >> 1;
        float* zb = g_z + (size_t)b * HW_ * C_;
        int zoff = n0 - C_;
        __syncthreads();
        #pragma unroll
        for (int j = 0; j < 2; j++) {
            if (wm == j) {
                #pragma unroll
                for (int mf = 0; mf < 4; mf++) {
                    int rl = mf * 16 + g;
                    #pragma unroll
                    for (int nf = 0; nf < 4; nf++) {
                        int cc = wn * 32 + nf * 8 + 2 * t4;
                        *(float2*)(sC + rl * 132 + cc) =
                            make_float2(acc[mf][nf][0], acc[mf][nf][1]);
                        *(float2*)(sC + (rl + 8) * 132 + cc) =
                            make_float2(acc[mf][nf][2], acc[mf][nf][3]);
                    }
                }
            }
            __syncthreads();
            for (int i = tid; i < 2048; i += 256) {
                int row = i >> 5, q = i & 31;
                float4 v = *(float4*)(sC + row * 132 + 4 * q);
                float4 bb = *(const float4*)(lb + C_ + zoff + 4 * q);
                v.x += bb.x; v.y += bb.y; v.z += bb.z; v.w += bb.w;
                *(float4*)(zb + (size_t)(m0 + 64 * j + row) * C_ + zoff + 4 * q) = v;
            }
            __syncthreads();
        }
    }
}

// ---------------------------------------------------------------------------
// gate GEMM: t = relu(fe @ tok_w^T + tok_b); gate = cos(c*t)+sin(c*t)*(1+.5a)/c
// ---------------------------------------------------------------------------
struct GateXform {
    const float* tb;
    float c0, s1;
    __device__ float operator()(float v, int ch) const {
        float t = fmaxf(v + tb[ch], 0.0f);
        float ct = c0 * t;
        return cosf(ct) + sinf(ct) * s1;
    }
};

__global__ void __launch_bounds__(256, 2) k_gate_mma(const float* __restrict__ fe,
                                                     const float* __restrict__ tw,
                                                     const float* __restrict__ tb,
                                                     const float* __restrict__ cp,
                                                     const float* __restrict__ ap) {
    extern __shared__ __align__(16) uint32_t sm[];
    int tid = threadIdx.x;
    int m0 = blockIdx.x * 128, n0 = blockIdx.y * 128;
    float acc[4][4][4];
    #pragma unroll
    for (int i = 0; i < 4; i++)
        #pragma unroll
        for (int j = 0; j < 4; j++)
            #pragma unroll
            for (int k = 0; k < 4; k++) acc[i][j][k] = 0.0f;

    gemm_core<1>(fe, C_, tw, m0, n0, tid, sm, acc);

    float c0 = cp[0];
    float s1 = (1.0f + 0.5f * ap[0]) / c0;
    epi_nchw(sm, acc, tid, g_gate, HW_, m0, n0, GateXform{tb, c0, s1});
}

// ---------------------------------------------------------------------------
// out GEMM: out[d][m] = sum_c y[m][c]*out_w[d][c] + out_b[d]
// ---------------------------------------------------------------------------
__global__ void __launch_bounds__(256, 2) k_out_mma(const float* __restrict__ ow,
                                                    const float* __restrict__ ob,
                                                    float* __restrict__ out) {
    extern __shared__ __align__(16) uint32_t sm[];
    int tid = threadIdx.x;
    int b = blockIdx.z, m0 = blockIdx.x * 128, n0 = blockIdx.y * 128;
    float acc[4][4][4];
    #pragma unroll
    for (int i = 0; i < 4; i++)
        #pragma unroll
        for (int j = 0; j < 4; j++)
            #pragma unroll
            for (int k = 0; k < 4; k++) acc[i][j][k] = 0.0f;

    gemm_core<1>(g_buf1 + (size_t)b * HW_ * C_, C_, ow, m0, n0, tid, sm, acc);

    epi_nchw(sm, acc, tid, out + (size_t)b * C_ * HW_, HW_, m0, n0, AddBias{ob});
}

// ===========================================================================
// Fused DCT -> gate -> iDCT per (b,c) image, tf32 mma (round-3 layout:
// one image per block, 58 KB smem, 8 warps, warp tile 16x32).
// ---------------------------------------------------------------------------
#define DS 76
#define DTILE (64 * DS)
#define DCT_SMEM_BYTES (3 * DTILE * 4)

__device__ __forceinline__ void dct_mm(const uint32_t* __restrict__ pA,
                                       const uint32_t* __restrict__ pB,
                                       float acc[4][4], int r, int nb,
                                       int g, int t4) {
    #pragma unroll
    for (int nf = 0; nf < 4; nf++)
        #pragma unroll
        for (int j = 0; j < 4; j++) acc[nf][j] = 0.0f;
    #pragma unroll
    for (int k8 = 0; k8 < 8; k8++) {
        uint32_t a0 = pA[r * DS + k8 * 8 + t4];
        uint32_t a1 = pA[(r + 8) * DS + k8 * 8 + t4];
        uint32_t a2 = pA[r * DS + k8 * 8 + t4 + 4];
        uint32_t a3 = pA[(r + 8) * DS + k8 * 8 + t4 + 4];
        #pragma unroll
        for (int nf = 0; nf < 4; nf++) {
            int n = nb + nf * 8 + g;
            uint32_t b0 = pB[(k8 * 8 + t4) * DS + n];
            uint32_t b1 = pB[(k8 * 8 + t4 + 4) * DS + n];
            mma8(acc[nf], a0, a1, a2, a3, b0, b1);
        }
    }
}

__global__ void __launch_bounds__(256) k_dct_mma() {
    extern __shared__ uint32_t dsm[];
    uint32_t* tW = dsm;
    uint32_t* tA = dsm + DTILE;
    uint32_t* tB = dsm + 2 * DTILE;
    int bc = blockIdx.x;
    int c = bc % C_;
    int tid = threadIdx.x;
    const float* xim = g_buf1 + (size_t)bc * HW_;
    for (int i = tid; i < 4096; i += 256) {
        int h = i >> 6, w = i & 63;
        tW[h * DS + w] = f2tf(g_W[i]);
        tA[h * DS + w] = f2tf(xim[i]);
    }
    __syncthreads();

    int lane = tid & 31, g = lane >> 2, t4 = lane & 3;
    int warp = tid >> 5, wm = warp & 3, wn = warp >> 2;
    int r = wm * 16 + g, nb = wn * 32;
    float acc[4][4];

    // mm1: M1[n][w] = sum_h W[n][h] X[h][w]  -> store transposed tB[w][n]
    dct_mm(tW, tA, acc, r, nb, g, t4);
    #pragma unroll
    for (int nf = 0; nf < 4; nf++) {
        int cc = nb + nf * 8 + 2 * t4;
        tB[cc * DS + r]           = f2tf(acc[nf][0]);
        tB[(cc + 1) * DS + r]     = f2tf(acc[nf][1]);
        tB[cc * DS + r + 8]       = f2tf(acc[nf][2]);
        tB[(cc + 1) * DS + r + 8] = f2tf(acc[nf][3]);
    }
    __syncthreads();

    // mm2: XdT[k][n] = sum_w W[k][w] M1T[w][n]; gate; store tA[k][n]
    dct_mm(tW, tB, acc, r, nb, g, t4);
    {
        const float* gp = g_gate + (size_t)c * HW_;
        #pragma unroll
        for (int nf = 0; nf < 4; nf++) {
            int cc = nb + nf * 8 + 2 * t4;
            float g0 = gp[cc * 64 + r];
            float g1 = gp[(cc + 1) * 64 + r];
            float g2 = gp[cc * 64 + r + 8];
            float g3 = gp[(cc + 1) * 64 + r + 8];
            tA[r * DS + cc]           = f2tf(acc[nf][0] * g0);
            tA[r * DS + cc + 1]       = f2tf(acc[nf][1] * g1);
            tA[(r + 8) * DS + cc]     = f2tf(acc[nf][2] * g2);
            tA[(r + 8) * DS + cc + 1] = f2tf(acc[nf][3] * g3);
        }
    }
    __syncthreads();

    // mm3: M2T[k][h] = sum_n F[k][n] W[n][h] -> store transposed tB[h][k]
    dct_mm(tA, tW, acc, r, nb, g, t4);
    #pragma unroll
    for (int nf = 0; nf < 4; nf++) {
        int cc = nb + nf * 8 + 2 * t4;
        tB[cc * DS + r]           = f2tf(acc[nf][0]);
        tB[(cc + 1) * DS + r]     = f2tf(acc[nf][1]);
        tB[cc * DS + r + 8]       = f2tf(acc[nf][2]);
        tB[(cc + 1) * DS + r + 8] = f2tf(acc[nf][3]);
    }
    __syncthreads();

    // mm4: xi[h][w] = sum_k M2T[k][h] W[k][w] -> gmem
    dct_mm(tB, tW, acc, r, nb, g, t4);
    float* xo = g_buf0 + (size_t)bc * HW_;
    #pragma unroll
    for (int nf = 0; nf < 4; nf++) {
        int cc = nb + nf * 8 + 2 * t4;
        *(float2*)(xo + r * 64 + cc)       = make_float2(acc[nf][0], acc[nf][1]);
        *(float2*)(xo + (r + 8) * 64 + cc) = make_float2(acc[nf][2], acc[nf][3]);
    }
}

// ---------------------------------------------------------------------------
// LayerNorm over channels + SiLU(z) gate. 16 tokens per block of 128 threads.
// ---------------------------------------------------------------------------
__global__ void k_ln(const float* __restrict__ lng, const float* __restrict__ lnb) {
    __shared__ float s[C_ * 17];
    int tid = threadIdx.x;
    int mglob = blockIdx.x * 16;
    int b = mglob >> 12;
    int mloc = mglob & 4095;
    const float* xi = g_buf0 + (size_t)b * C_ * HW_ + mloc;
    for (int i = tid; i < C_ * 16; i += 128) {
        int cc = i >> 4, t = i & 15;
        s[cc * 17 + t] = xi[(size_t)cc * HW_ + t];
    }
    __syncthreads();
    int tk = tid >> 3, g = tid & 7;
    float sum = 0.0f, ss = 0.0f;
    #pragma unroll 8
    for (int ii = 0; ii < 48; ii++) {
        int cc = g + ii * 8;
        float v = s[cc * 17 + tk];
        sum += v; ss += v * v;
    }
    #pragma unroll
    for (int off = 4; off; off >>= 1) {
        sum += __shfl_down_sync(0xffffffffu, sum, off);
        ss  += __shfl_down_sync(0xffffffffu, ss,  off);
    }
    int lane = tid & 31;
    int src = lane & ~7;
    sum = __shfl_sync(0xffffffffu, sum, src);
    ss  = __shfl_sync(0xffffffffu, ss,  src);
    float mu = sum * (1.0f / 384.0f);
    float var = ss * (1.0f / 384.0f) - mu * mu;
    float rstd = rsqrtf(fmaxf(var, 0.0f) + 1e-5f);

    int mt = mloc + tk;
    const float* zp = g_z + ((size_t)b * HW_ + mt) * C_;
    float* yp = g_buf1 + ((size_t)b * HW_ + mt) * C_;
    #pragma unroll 4
    for (int ii = 0; ii < 12; ii++) {
        int c0 = g * 48 + ii * 4;
        float4 zv = *(const float4*)(zp + c0);
        float4 gg = *(const float4*)(lng + c0);
        float4 bb = *(const float4*)(lnb + c0);
        float y0 = (s[(c0 + 0) * 17 + tk] - mu) * rstd * gg.x + bb.x;
        float y1 = (s[(c0 + 1) * 17 + tk] - mu) * rstd * gg.y + bb.y;
        float y2 = (s[(c0 + 2) * 17 + tk] - mu) * rstd * gg.z + bb.z;
        float y3 = (s[(c0 + 3) * 17 + tk] - mu) * rstd * gg.w + bb.w;
        y0 *= zv.x / (1.0f + __expf(-zv.x));
        y1 *= zv.y / (1.0f + __expf(-zv.y));
        y2 *= zv.z / (1.0f + __expf(-zv.z));
        y3 *= zv.w / (1.0f + __expf(-zv.w));
        *(float4*)(yp + c0) = make_float4(y0, y1, y2, y3);
    }
}

// ---------------------------------------------------------------------------
extern "C" void kernel_launch(void* const* d_in, const int* in_sizes, int n_in,
                              void* d_out, int out_size) {
    const float* x     = (const float*)d_in[0];
    const float* fe    = (const float*)d_in[1];
    const float* dw_w  = (const float*)d_in[2];
    const float* dw_b  = (const float*)d_in[3];
    const float* lin_w = (const float*)d_in[4];
    const float* lin_b = (const float*)d_in[5];
    const float* tok_w = (const float*)d_in[6];
    const float* tok_b = (const float*)d_in[7];
    const float* cc    = (const float*)d_in[8];
    const float* alpha = (const float*)d_in[9];
    const float* ln_g  = (const float*)d_in[10];
    const float* ln_b  = (const float*)d_in[11];
    const float* out_w = (const float*)d_in[12];
    const float* out_b = (const float*)d_in[13];
    float* out = (float*)d_out;

    cudaFuncSetAttribute(k_dct_mma, cudaFuncAttributeMaxDynamicSharedMemorySize,
                         DCT_SMEM_BYTES);
    cudaFuncSetAttribute(k_lin_mma, cudaFuncAttributeMaxDynamicSharedMemorySize,
                         GEMM_SMEM_BYTES);
    cudaFuncSetAttribute(k_gate_mma, cudaFuncAttributeMaxDynamicSharedMemorySize,
                         GEMM_SMEM_BYTES);
    cudaFuncSetAttribute(k_out_mma, cudaFuncAttributeMaxDynamicSharedMemorySize,
                         GEMM_SMEM_BYTES);

    k_dct_basis<<<64, 64>>>();
    k_dwconv<<<B_ * C_, 256>>>(x, dw_w, dw_b);
    k_gate_mma<<<dim3(32, 3), 256, GEMM_SMEM_BYTES>>>(fe, tok_w, tok_b, cc, alpha);
    k_lin_mma<<<dim3(32, 6, B_), 256, GEMM_SMEM_BYTES>>>(lin_w, lin_b);
    k_dct_mma<<<B_ * C_, 256, DCT_SMEM_BYTES>>>();
    k_ln<<<(B_ * HW_) / 16, 128>>>(ln_g, ln_b);
    k_out_mma<<<dim3(32, 3, B_), 256, GEMM_SMEM_BYTES>>>(out_w, out_b, out);
}

// round 9
// speedup vs baseline: 1.4211x; 1.4211x over previous
#include <cuda_runtime.h>
#include <math.h>
#include <stdint.h>

#define B_ 8
#define C_ 384
#define HW_ 4096

// Scratch (device globals — no runtime allocation)
__device__ float g_buf0[B_ * C_ * HW_];   // xdw, later xi
__device__ float g_buf1[B_ * C_ * HW_];   // xs,  later y
__device__ float g_z[B_ * HW_ * C_];      // z token-major
__device__ float g_gate[C_ * HW_];        // spectral gate [c][n*64+k]
__device__ float g_W[64 * 64];            // DCT-II basis (Wh == Ww)

// ---------------------------------------------------------------------------
// helpers
// ---------------------------------------------------------------------------
__device__ __forceinline__ uint32_t f2tf(float f) {
    uint32_t u;
    asm("cvt.rna.tf32.f32 %0, %1;" : "=r"(u) : "f"(f));
    return u;
}
__device__ __forceinline__ uint32_t f2tf_u(uint32_t raw) {
    return f2tf(__uint_as_float(raw));
}

__device__ __forceinline__ void mma8(float* c, uint32_t a0, uint32_t a1,
                                     uint32_t a2, uint32_t a3,
                                     uint32_t b0, uint32_t b1) {
    asm volatile(
        "mma.sync.aligned.m16n8k8.row.col.f32.tf32.tf32.f32 "
        "{%0,%1,%2,%3}, {%4,%5,%6,%7}, {%8,%9}, {%0,%1,%2,%3};"
        : "+f"(c[0]), "+f"(c[1]), "+f"(c[2]), "+f"(c[3])
        : "r"(a0), "r"(a1), "r"(a2), "r"(a3), "r"(b0), "r"(b1));
}

__device__ __forceinline__ void cp16(uint32_t dst_smem, const void* src) {
    asm volatile("cp.async.cg.shared.global [%0], [%1], 16;"
                 :: "r"(dst_smem), "l"(src));
}

// ---------------------------------------------------------------------------
// DCT basis
// ---------------------------------------------------------------------------
__global__ void k_dct_basis() {
    int n = blockIdx.x, x = threadIdx.x;
    float v = cosf((float)n * ((float)x + 0.5f) * (3.14159265358979323846f / 64.0f))
              * 0.17677669529663687f;
    if (n == 0) v *= 0.70710678118654752f;
    g_W[n * 64 + x] = v;
}

// ---------------------------------------------------------------------------
// Depthwise 3x3 conv (SAME) + bias. One block per (b,c) image.
// ---------------------------------------------------------------------------
__global__ void k_dwconv(const float* __restrict__ x,
                         const float* __restrict__ w,
                         const float* __restrict__ bias) {
    __shared__ float s[66 * 68];
    int bc = blockIdx.x;
    const float* xim = x + (size_t)bc * HW_;
    int tid = threadIdx.x;
    for (int i = tid; i < 66 * 66; i += 256) {
        int r = i / 66, cl = i % 66;
        int gh = r - 1, gw = cl - 1;
        float v = 0.0f;
        if ((unsigned)gh < 64u && (unsigned)gw < 64u) v = xim[gh * 64 + gw];
        s[r * 68 + cl] = v;
    }
    int c = bc % C_;
    const float* wp = w + c * 9;
    float w0 = wp[0], w1 = wp[1], w2 = wp[2];
    float w3 = wp[3], w4 = wp[4], w5 = wp[5];
    float w6 = wp[6], w7 = wp[7], w8 = wp[8];
    float bv = bias[c];
    __syncthreads();
    float* outp = g_buf0 + (size_t)bc * HW_;
    for (int p = tid; p < HW_; p += 256) {
        int h = p >> 6, ww = p & 63;
        const float* sp = s + h * 68 + ww;
        float acc = bv;
        acc = fmaf(sp[0],   w0, acc); acc = fmaf(sp[1],   w1, acc); acc = fmaf(sp[2],   w2, acc);
        acc = fmaf(sp[68],  w3, acc); acc = fmaf(sp[69],  w4, acc); acc = fmaf(sp[70],  w5, acc);
        acc = fmaf(sp[136], w6, acc); acc = fmaf(sp[137], w7, acc); acc = fmaf(sp[138], w8, acc);
        outp[p] = acc;
    }
}

// ===========================================================================
// GEMM core v4: block 128(M) x 128(N), 128 threads = 4 warps (2m x 2n),
// warp tile 64x64 (4 m-frags x 8 n-frags) — the proven round-4 shape —
// with a 3-stage cp.async ring replacing LDG+cvt+STS staging. Raw f32 is
// staged; cvt.rna.tf32 happens at fragment load (same op per element, same
// K order -> bit-identical numerics to rounds 3/4).
// smem per stage: sA (128*36 words; AMODE0 uses [32][136] transposed) +
// sB [128][36]. 3 stages x 36864 B = 110592 B dynamic.
// AMODE 0: A gmem [K][M] (m contiguous)  -> smem k-major [32][136]
// AMODE 1: A gmem [M][K] (k contiguous)  -> smem m-major [128][36]
// B gmem [N][K], k contiguous (ld = 384) -> smem [128][36]
// ---------------------------------------------------------------------------
#define STG_WORDS (2 * 128 * 36)                 // words per stage
#define GEMM_SMEM_BYTES (3 * STG_WORDS * 4)      // 110592

template<int AMODE>
__device__ __forceinline__ void stage_cp(uint32_t sbase, const float* __restrict__ Ag,
                                         int lda, const float* __restrict__ Bg,
                                         int m0, int n0, int kt, int tid) {
    if (AMODE == 0) {
        #pragma unroll
        for (int j = 0; j < 8; j++) {
            int id = tid + 128 * j;
            int kk = id >> 5, mc = (id & 31) * 4;
            cp16(sbase + (kk * 136 + mc) * 4,
                 Ag + (size_t)(kt + kk) * lda + m0 + mc);
        }
    } else {
        #pragma unroll
        for (int j = 0; j < 8; j++) {
            int k4 = tid & 7, mm = (tid >> 3) + 16 * j;
            cp16(sbase + (mm * 36 + 4 * k4) * 4,
                 Ag + (size_t)(m0 + mm) * lda + kt + 4 * k4);
        }
    }
    #pragma unroll
    for (int j = 0; j < 8; j++) {
        int k4 = tid & 7, nn = (tid >> 3) + 16 * j;
        cp16(sbase + (128 * 36 + nn * 36 + 4 * k4) * 4,
             Bg + (size_t)(n0 + nn) * C_ + kt + 4 * k4);
    }
    asm volatile("cp.async.commit_group;" ::: "memory");
}

template<int AMODE>
__device__ __forceinline__ void gemm_core(const float* __restrict__ Ag, int lda,
                                          const float* __restrict__ Bg,
                                          int m0, int n0, int tid,
                                          uint32_t* sm, float acc[4][8][4]) {
    int lane = tid & 31, g = lane >> 2, t4 = lane & 3;
    int warp = tid >> 5, wm = warp & 1, wn = warp >> 1;
    uint32_t sb = (uint32_t)__cvta_generic_to_shared(sm);

    stage_cp<AMODE>(sb,                 Ag, lda, Bg, m0, n0, 0,  tid);
    stage_cp<AMODE>(sb + STG_WORDS * 4, Ag, lda, Bg, m0, n0, 32, tid);

    #pragma unroll 1
    for (int kc = 0; kc < 12; kc++) {
        if (kc == 11) asm volatile("cp.async.wait_group 0;" ::: "memory");
        else          asm volatile("cp.async.wait_group 1;" ::: "memory");
        __syncthreads();
        if (kc + 2 < 12)
            stage_cp<AMODE>(sb + ((kc + 2) % 3) * STG_WORDS * 4,
                            Ag, lda, Bg, m0, n0, (kc + 2) * 32, tid);

        const uint32_t* sA = sm + (kc % 3) * STG_WORDS;
        const uint32_t* sB = sA + 128 * 36;
        #pragma unroll
        for (int k8 = 0; k8 < 4; k8++) {
            uint32_t a[4][4], bq[8][2];
            #pragma unroll
            for (int mf = 0; mf < 4; mf++) {
                int m = wm * 64 + mf * 16 + g;
                if (AMODE == 0) {
                    a[mf][0] = f2tf_u(sA[(k8 * 8 + t4) * 136 + m]);
                    a[mf][1] = f2tf_u(sA[(k8 * 8 + t4) * 136 + m + 8]);
                    a[mf][2] = f2tf_u(sA[(k8 * 8 + t4 + 4) * 136 + m]);
                    a[mf][3] = f2tf_u(sA[(k8 * 8 + t4 + 4) * 136 + m + 8]);
                } else {
                    const uint32_t* pa = sA + m * 36 + k8 * 8 + t4;
                    a[mf][0] = f2tf_u(pa[0]);
                    a[mf][1] = f2tf_u(pa[8 * 36]);
                    a[mf][2] = f2tf_u(pa[4]);
                    a[mf][3] = f2tf_u(pa[8 * 36 + 4]);
                }
            }
            #pragma unroll
            for (int nf = 0; nf < 8; nf++) {
                const uint32_t* pb = sB + (wn * 64 + nf * 8 + g) * 36 + k8 * 8 + t4;
                bq[nf][0] = f2tf_u(pb[0]);
                bq[nf][1] = f2tf_u(pb[4]);
            }
            #pragma unroll
            for (int mf = 0; mf < 4; mf++)
                #pragma unroll
                for (int nf = 0; nf < 8; nf++)
                    mma8(acc[mf][nf], a[mf][0], a[mf][1], a[mf][2], a[mf][3],
                         bq[nf][0], bq[nf][1]);
        }
        __syncthreads();
    }
}

// Chunked NCHW epilogue (round-4 layout): 4 chunks of 32 channels, staged
// [ch][m] stride 132 (conflict-free).
template<typename F>
__device__ __forceinline__ void epi_nchw(uint32_t* sm, float acc[4][8][4],
                                         int tid, float* dst, int strideM,
                                         int m0, int n0, F f) {
    float* sC = (float*)sm;
    int lane = tid & 31, g = lane >> 2, t4 = lane & 3;
    int warp = tid >> 5, wm = warp & 1, wn = warp >> 1;
    #pragma unroll
    for (int c = 0; c < 4; c++) {
        if (wn == (c >> 1)) {
            int nf0 = 4 * (c & 1);
            #pragma unroll
            for (int mf = 0; mf < 4; mf++) {
                int r = wm * 64 + mf * 16 + g;
                #pragma unroll
                for (int nfl = 0; nfl < 4; nfl++) {
                    int nf = nf0 + nfl;
                    int chl = nfl * 8 + 2 * t4;
                    sC[chl * 132 + r]           = acc[mf][nf][0];
                    sC[(chl + 1) * 132 + r]     = acc[mf][nf][1];
                    sC[chl * 132 + r + 8]       = acc[mf][nf][2];
                    sC[(chl + 1) * 132 + r + 8] = acc[mf][nf][3];
                }
            }
        }
        __syncthreads();
        for (int i = tid; i < 4096; i += 128) {
            int ch = i >> 7, mm = i & 127;
            int gc = n0 + 32 * c + ch;
            dst[(size_t)gc * strideM + m0 + mm] = f(sC[ch * 132 + mm], gc);
        }
        __syncthreads();
    }
}

// ---------------------------------------------------------------------------
// lin GEMM: xz[m][d] = sum_c xdw[c][m]*lin_w[d][c] + lin_b[d]
// by 0..2 -> xs (NCHW); by 3..5 -> z (token-major)
// ---------------------------------------------------------------------------
struct AddBias {
    const float* b;
    __device__ float operator()(float v, int ch) const { return v + b[ch]; }
};

__global__ void __launch_bounds__(128, 2) k_lin_mma(const float* __restrict__ lw,
                                                    const float* __restrict__ lb) {
    extern __shared__ __align__(16) uint32_t sm[];
    int tid = threadIdx.x;
    int b = blockIdx.z, m0 = blockIdx.x * 128, n0 = blockIdx.y * 128;
    float acc[4][8][4];
    #pragma unroll
    for (int i = 0; i < 4; i++)
        #pragma unroll
        for (int j = 0; j < 8; j++)
            #pragma unroll
            for (int k = 0; k < 4; k++) acc[i][j][k] = 0.0f;

    gemm_core<0>(g_buf0 + (size_t)b * C_ * HW_, HW_, lw, m0, n0, tid, sm, acc);

    if (n0 < C_) {
        epi_nchw(sm, acc, tid, g_buf1 + (size_t)b * C_ * HW_, HW_, m0, n0,
                 AddBias{lb});
    } else {
        // z half -> token-major [m][C_], 2 chunks of 64 rows (by wm)
        float* sC = (float*)sm;
        int lane = tid & 31, g = lane >> 2, t4 = lane & 3;
        int warp = tid >> 5, wm = warp & 1, wn = warp >> 1;
        float* zb = g_z + (size_t)b * HW_ * C_;
        int zoff = n0 - C_;
        #pragma unroll
        for (int j = 0; j < 2; j++) {
            if (wm == j) {
                #pragma unroll
                for (int mf = 0; mf < 4; mf++) {
                    int rl = mf * 16 + g;
                    #pragma unroll
                    for (int nf = 0; nf < 8; nf++) {
                        int cc = wn * 64 + nf * 8 + 2 * t4;
                        *(float2*)(sC + rl * 132 + cc) =
                            make_float2(acc[mf][nf][0], acc[mf][nf][1]);
                        *(float2*)(sC + (rl + 8) * 132 + cc) =
                            make_float2(acc[mf][nf][2], acc[mf][nf][3]);
                    }
                }
            }
            __syncthreads();
            for (int i = tid; i < 2048; i += 128) {
                int row = i >> 5, q = i & 31;
                float4 v = *(float4*)(sC + row * 132 + 4 * q);
                float4 bb = *(const float4*)(lb + C_ + zoff + 4 * q);
                v.x += bb.x; v.y += bb.y; v.z += bb.z; v.w += bb.w;
                *(float4*)(zb + (size_t)(m0 + 64 * j + row) * C_ + zoff + 4 * q) = v;
            }
            __syncthreads();
        }
    }
}

// ---------------------------------------------------------------------------
// gate GEMM: t = relu(fe @ tok_w^T + tok_b); gate = cos(c*t)+sin(c*t)*(1+.5a)/c
// ---------------------------------------------------------------------------
struct GateXform {
    const float* tb;
    float c0, s1;
    __device__ float operator()(float v, int ch) const {
        float t = fmaxf(v + tb[ch], 0.0f);
        float ct = c0 * t;
        return cosf(ct) + sinf(ct) * s1;
    }
};

__global__ void __launch_bounds__(128, 2) k_gate_mma(const float* __restrict__ fe,
                                                     const float* __restrict__ tw,
                                                     const float* __restrict__ tb,
                                                     const float* __restrict__ cp,
                                                     const float* __restrict__ ap) {
    extern __shared__ __align__(16) uint32_t sm[];
    int tid = threadIdx.x;
    int m0 = blockIdx.x * 128, n0 = blockIdx.y * 128;
    float acc[4][8][4];
    #pragma unroll
    for (int i = 0; i < 4; i++)
        #pragma unroll
        for (int j = 0; j < 8; j++)
            #pragma unroll
            for (int k = 0; k < 4; k++) acc[i][j][k] = 0.0f;

    gemm_core<1>(fe, C_, tw, m0, n0, tid, sm, acc);

    float c0 = cp[0];
    float s1 = (1.0f + 0.5f * ap[0]) / c0;
    epi_nchw(sm, acc, tid, g_gate, HW_, m0, n0, GateXform{tb, c0, s1});
}

// ---------------------------------------------------------------------------
// out GEMM: out[d][m] = sum_c y[m][c]*out_w[d][c] + out_b[d]
// ---------------------------------------------------------------------------
__global__ void __launch_bounds__(128, 2) k_out_mma(const float* __restrict__ ow,
                                                    const float* __restrict__ ob,
                                                    float* __restrict__ out) {
    extern __shared__ __align__(16) uint32_t sm[];
    int tid = threadIdx.x;
    int b = blockIdx.z, m0 = blockIdx.x * 128, n0 = blockIdx.y * 128;
    float acc[4][8][4];
    #pragma unroll
    for (int i = 0; i < 4; i++)
        #pragma unroll
        for (int j = 0; j < 8; j++)
            #pragma unroll
            for (int k = 0; k < 4; k++) acc[i][j][k] = 0.0f;

    gemm_core<1>(g_buf1 + (size_t)b * HW_ * C_, C_, ow, m0, n0, tid, sm, acc);

    epi_nchw(sm, acc, tid, out + (size_t)b * C_ * HW_, HW_, m0, n0, AddBias{ob});
}

// ===========================================================================
// Fused DCT -> gate -> iDCT per (b,c) image, tf32 mma (round-3 layout:
// one image per block, 58 KB smem, 8 warps, warp tile 16x32).
// ---------------------------------------------------------------------------
#define DS 76
#define DTILE (64 * DS)
#define DCT_SMEM_BYTES (3 * DTILE * 4)

__device__ __forceinline__ void dct_mm(const uint32_t* __restrict__ pA,
                                       const uint32_t* __restrict__ pB,
                                       float acc[4][4], int r, int nb,
                                       int g, int t4) {
    #pragma unroll
    for (int nf = 0; nf < 4; nf++)
        #pragma unroll
        for (int j = 0; j < 4; j++) acc[nf][j] = 0.0f;
    #pragma unroll
    for (int k8 = 0; k8 < 8; k8++) {
        uint32_t a0 = pA[r * DS + k8 * 8 + t4];
        uint32_t a1 = pA[(r + 8) * DS + k8 * 8 + t4];
        uint32_t a2 = pA[r * DS + k8 * 8 + t4 + 4];
        uint32_t a3 = pA[(r + 8) * DS + k8 * 8 + t4 + 4];
        #pragma unroll
        for (int nf = 0; nf < 4; nf++) {
            int n = nb + nf * 8 + g;
            uint32_t b0 = pB[(k8 * 8 + t4) * DS + n];
            uint32_t b1 = pB[(k8 * 8 + t4 + 4) * DS + n];
            mma8(acc[nf], a0, a1, a2, a3, b0, b1);
        }
    }
}

__global__ void __launch_bounds__(256) k_dct_mma() {
    extern __shared__ uint32_t dsm[];
    uint32_t* tW = dsm;
    uint32_t* tA = dsm + DTILE;
    uint32_t* tB = dsm + 2 * DTILE;
    int bc = blockIdx.x;
    int c = bc % C_;
    int tid = threadIdx.x;
    const float* xim = g_buf1 + (size_t)bc * HW_;
    for (int i = tid; i < 4096; i += 256) {
        int h = i >> 6, w = i & 63;
        tW[h * DS + w] = f2tf(g_W[i]);
        tA[h * DS + w] = f2tf(xim[i]);
    }
    __syncthreads();

    int lane = tid & 31, g = lane >> 2, t4 = lane & 3;
    int warp = tid >> 5, wm = warp & 3, wn = warp >> 2;
    int r = wm * 16 + g, nb = wn * 32;
    float acc[4][4];

    // mm1: M1[n][w] = sum_h W[n][h] X[h][w]  -> store transposed tB[w][n]
    dct_mm(tW, tA, acc, r, nb, g, t4);
    #pragma unroll
    for (int nf = 0; nf < 4; nf++) {
        int cc = nb + nf * 8 + 2 * t4;
        tB[cc * DS + r]           = f2tf(acc[nf][0]);
        tB[(cc + 1) * DS + r]     = f2tf(acc[nf][1]);
        tB[cc * DS + r + 8]       = f2tf(acc[nf][2]);
        tB[(cc + 1) * DS + r + 8] = f2tf(acc[nf][3]);
    }
    __syncthreads();

    // mm2: XdT[k][n] = sum_w W[k][w] M1T[w][n]; gate; store tA[k][n]
    dct_mm(tW, tB, acc, r, nb, g, t4);
    {
        const float* gp = g_gate + (size_t)c * HW_;
        #pragma unroll
        for (int nf = 0; nf < 4; nf++) {
            int cc = nb + nf * 8 + 2 * t4;
            float g0 = gp[cc * 64 + r];
            float g1 = gp[(cc + 1) * 64 + r];
            float g2 = gp[cc * 64 + r + 8];
            float g3 = gp[(cc + 1) * 64 + r + 8];
            tA[r * DS + cc]           = f2tf(acc[nf][0] * g0);
            tA[r * DS + cc + 1]       = f2tf(acc[nf][1] * g1);
            tA[(r + 8) * DS + cc]     = f2tf(acc[nf][2] * g2);
            tA[(r + 8) * DS + cc + 1] = f2tf(acc[nf][3] * g3);
        }
    }
    __syncthreads();

    // mm3: M2T[k][h] = sum_n F[k][n] W[n][h] -> store transposed tB[h][k]
    dct_mm(tA, tW, acc, r, nb, g, t4);
    #pragma unroll
    for (int nf = 0; nf < 4; nf++) {
        int cc = nb + nf * 8 + 2 * t4;
        tB[cc * DS + r]           = f2tf(acc[nf][0]);
        tB[(cc + 1) * DS + r]     = f2tf(acc[nf][1]);
        tB[cc * DS + r + 8]       = f2tf(acc[nf][2]);
        tB[(cc + 1) * DS + r + 8] = f2tf(acc[nf][3]);
    }
    __syncthreads();

    // mm4: xi[h][w] = sum_k M2T[k][h] W[k][w] -> gmem
    dct_mm(tB, tW, acc, r, nb, g, t4);
    float* xo = g_buf0 + (size_t)bc * HW_;
    #pragma unroll
    for (int nf = 0; nf < 4; nf++) {
        int cc = nb + nf * 8 + 2 * t4;
        *(float2*)(xo + r * 64 + cc)       = make_float2(acc[nf][0], acc[nf][1]);
        *(float2*)(xo + (r + 8) * 64 + cc) = make_float2(acc[nf][2], acc[nf][3]);
    }
}

// ---------------------------------------------------------------------------
// LayerNorm over channels + SiLU(z) gate. 16 tokens per block of 128 threads.
// ---------------------------------------------------------------------------
__global__ void k_ln(const float* __restrict__ lng, const float* __restrict__ lnb) {
    __shared__ float s[C_ * 17];
    int tid = threadIdx.x;
    int mglob = blockIdx.x * 16;
    int b = mglob >> 12;
    int mloc = mglob & 4095;
    const float* xi = g_buf0 + (size_t)b * C_ * HW_ + mloc;
    for (int i = tid; i < C_ * 16; i += 128) {
        int cc = i >> 4, t = i & 15;
        s[cc * 17 + t] = xi[(size_t)cc * HW_ + t];
    }
    __syncthreads();
    int tk = tid >> 3, g = tid & 7;
    float sum = 0.0f, ss = 0.0f;
    #pragma unroll 8
    for (int ii = 0; ii < 48; ii++) {
        int cc = g + ii * 8;
        float v = s[cc * 17 + tk];
        sum += v; ss += v * v;
    }
    #pragma unroll
    for (int off = 4; off; off >>= 1) {
        sum += __shfl_down_sync(0xffffffffu, sum, off);
        ss  += __shfl_down_sync(0xffffffffu, ss,  off);
    }
    int lane = tid & 31;
    int src = lane & ~7;
    sum = __shfl_sync(0xffffffffu, sum, src);
    ss  = __shfl_sync(0xffffffffu, ss,  src);
    float mu = sum * (1.0f / 384.0f);
    float var = ss * (1.0f / 384.0f) - mu * mu;
    float rstd = rsqrtf(fmaxf(var, 0.0f) + 1e-5f);

    int mt = mloc + tk;
    const float* zp = g_z + ((size_t)b * HW_ + mt) * C_;
    float* yp = g_buf1 + ((size_t)b * HW_ + mt) * C_;
    #pragma unroll 4
    for (int ii = 0; ii < 12; ii++) {
        int c0 = g * 48 + ii * 4;
        float4 zv = *(const float4*)(zp + c0);
        float4 gg = *(const float4*)(lng + c0);
        float4 bb = *(const float4*)(lnb + c0);
        float y0 = (s[(c0 + 0) * 17 + tk] - mu) * rstd * gg.x + bb.x;
        float y1 = (s[(c0 + 1) * 17 + tk] - mu) * rstd * gg.y + bb.y;
        float y2 = (s[(c0 + 2) * 17 + tk] - mu) * rstd * gg.z + bb.z;
        float y3 = (s[(c0 + 3) * 17 + tk] - mu) * rstd * gg.w + bb.w;
        y0 *= zv.x / (1.0f + __expf(-zv.x));
        y1 *= zv.y / (1.0f + __expf(-zv.y));
        y2 *= zv.z / (1.0f + __expf(-zv.z));
        y3 *= zv.w / (1.0f + __expf(-zv.w));
        *(float4*)(yp + c0) = make_float4(y0, y1, y2, y3);
    }
}

// ---------------------------------------------------------------------------
extern "C" void kernel_launch(void* const* d_in, const int* in_sizes, int n_in,
                              void* d_out, int out_size) {
    const float* x     = (const float*)d_in[0];
    const float* fe    = (const float*)d_in[1];
    const float* dw_w  = (const float*)d_in[2];
    const float* dw_b  = (const float*)d_in[3];
    const float* lin_w = (const float*)d_in[4];
    const float* lin_b = (const float*)d_in[5];
    const float* tok_w = (const float*)d_in[6];
    const float* tok_b = (const float*)d_in[7];
    const float* cc    = (const float*)d_in[8];
    const float* alpha = (const float*)d_in[9];
    const float* ln_g  = (const float*)d_in[10];
    const float* ln_b  = (const float*)d_in[11];
    const float* out_w = (const float*)d_in[12];
    const float* out_b = (const float*)d_in[13];
    float* out = (float*)d_out;

    cudaFuncSetAttribute(k_dct_mma, cudaFuncAttributeMaxDynamicSharedMemorySize,
                         DCT_SMEM_BYTES);
    cudaFuncSetAttribute(k_lin_mma, cudaFuncAttributeMaxDynamicSharedMemorySize,
                         GEMM_SMEM_BYTES);
    cudaFuncSetAttribute(k_gate_mma, cudaFuncAttributeMaxDynamicSharedMemorySize,
                         GEMM_SMEM_BYTES);
    cudaFuncSetAttribute(k_out_mma, cudaFuncAttributeMaxDynamicSharedMemorySize,
                         GEMM_SMEM_BYTES);

    k_dct_basis<<<64, 64>>>();
    k_dwconv<<<B_ * C_, 256>>>(x, dw_w, dw_b);
    k_gate_mma<<<dim3(32, 3), 128, GEMM_SMEM_BYTES>>>(fe, tok_w, tok_b, cc, alpha);
    k_lin_mma<<<dim3(32, 6, B_), 128, GEMM_SMEM_BYTES>>>(lin_w, lin_b);
    k_dct_mma<<<B_ * C_, 256, DCT_SMEM_BYTES>>>();
    k_ln<<<(B_ * HW_) / 16, 128>>>(ln_g, ln_b);
    k_out_mma<<<dim3(32, 3, B_), 128, GEMM_SMEM_BYTES>>>(out_w, out_b, out);
}

// round 10
// speedup vs baseline: 1.4771x; 1.0394x over previous
#include <cuda_runtime.h>
#include <math.h>
#include <stdint.h>

#define B_ 8
#define C_ 384
#define HW_ 4096

// Scratch (device globals — no runtime allocation)
__device__ float g_buf0[B_ * C_ * HW_];   // xdw (pre-rounded tf32), later xi
__device__ float g_buf1[B_ * C_ * HW_];   // xs, later y (pre-rounded tf32)
__device__ float g_z[B_ * HW_ * C_];      // z token-major (full f32)
__device__ float g_gate[C_ * HW_];        // spectral gate [c][n*64+k]
__device__ float g_W[64 * 64];            // DCT-II basis (Wh == Ww)
// pre-rounded (tf32-bit) copies of GEMM inputs
__device__ float g_feR[HW_ * C_];
__device__ float g_lwR[2 * C_ * C_];
__device__ float g_twR[C_ * C_];
__device__ float g_owR[C_ * C_];

// ---------------------------------------------------------------------------
// helpers
// ---------------------------------------------------------------------------
__device__ __forceinline__ uint32_t f2tf(float f) {
    uint32_t u;
    asm("cvt.rna.tf32.f32 %0, %1;" : "=r"(u) : "f"(f));
    return u;
}
__device__ __forceinline__ float f2tf_f(float f) {
    return __uint_as_float(f2tf(f));
}

__device__ __forceinline__ void mma8(float* c, uint32_t a0, uint32_t a1,
                                     uint32_t a2, uint32_t a3,
                                     uint32_t b0, uint32_t b1) {
    asm volatile(
        "mma.sync.aligned.m16n8k8.row.col.f32.tf32.tf32.f32 "
        "{%0,%1,%2,%3}, {%4,%5,%6,%7}, {%8,%9}, {%0,%1,%2,%3};"
        : "+f"(c[0]), "+f"(c[1]), "+f"(c[2]), "+f"(c[3])
        : "r"(a0), "r"(a1), "r"(a2), "r"(a3), "r"(b0), "r"(b1));
}

__device__ __forceinline__ void cp16(uint32_t dst_smem, const void* src) {
    asm volatile("cp.async.cg.shared.global [%0], [%1], 16;"
                 :: "r"(dst_smem), "l"(src));
}

// ---------------------------------------------------------------------------
// Pre-round inputs to tf32 bit patterns (idempotent with later mma rounding).
// which: 0 = fe, 1 = lin_w, 2 = tok_w, 3 = out_w
// ---------------------------------------------------------------------------
__global__ void k_round(const float* __restrict__ src, int which, int n4) {
    int i = blockIdx.x * blockDim.x + threadIdx.x;
    if (i >= n4) return;
    float* dst = which == 0 ? g_feR : which == 1 ? g_lwR
               : which == 2 ? g_twR : g_owR;
    float4 v = ((const float4*)src)[i];
    v.x = f2tf_f(v.x); v.y = f2tf_f(v.y);
    v.z = f2tf_f(v.z); v.w = f2tf_f(v.w);
    ((float4*)dst)[i] = v;
}

// ---------------------------------------------------------------------------
// DCT basis
// ---------------------------------------------------------------------------
__global__ void k_dct_basis() {
    int n = blockIdx.x, x = threadIdx.x;
    float v = cosf((float)n * ((float)x + 0.5f) * (3.14159265358979323846f / 64.0f))
              * 0.17677669529663687f;
    if (n == 0) v *= 0.70710678118654752f;
    g_W[n * 64 + x] = v;
}

// ---------------------------------------------------------------------------
// Depthwise 3x3 conv (SAME) + bias. One block per (b,c) image.
// Output written tf32-pre-rounded (consumed only by lin GEMM).
// ---------------------------------------------------------------------------
__global__ void k_dwconv(const float* __restrict__ x,
                         const float* __restrict__ w,
                         const float* __restrict__ bias) {
    __shared__ float s[66 * 68];
    int bc = blockIdx.x;
    const float* xim = x + (size_t)bc * HW_;
    int tid = threadIdx.x;
    for (int i = tid; i < 66 * 66; i += 256) {
        int r = i / 66, cl = i % 66;
        int gh = r - 1, gw = cl - 1;
        float v = 0.0f;
        if ((unsigned)gh < 64u && (unsigned)gw < 64u) v = xim[gh * 64 + gw];
        s[r * 68 + cl] = v;
    }
    int c = bc % C_;
    const float* wp = w + c * 9;
    float w0 = wp[0], w1 = wp[1], w2 = wp[2];
    float w3 = wp[3], w4 = wp[4], w5 = wp[5];
    float w6 = wp[6], w7 = wp[7], w8 = wp[8];
    float bv = bias[c];
    __syncthreads();
    float* outp = g_buf0 + (size_t)bc * HW_;
    for (int p = tid; p < HW_; p += 256) {
        int h = p >> 6, ww = p & 63;
        const float* sp = s + h * 68 + ww;
        float acc = bv;
        acc = fmaf(sp[0],   w0, acc); acc = fmaf(sp[1],   w1, acc); acc = fmaf(sp[2],   w2, acc);
        acc = fmaf(sp[68],  w3, acc); acc = fmaf(sp[69],  w4, acc); acc = fmaf(sp[70],  w5, acc);
        acc = fmaf(sp[136], w6, acc); acc = fmaf(sp[137], w7, acc); acc = fmaf(sp[138], w8, acc);
        outp[p] = f2tf_f(acc);
    }
}

// ===========================================================================
// GEMM core v5: block 128(M) x 128(N), 128 threads = 4 warps (2m x 2n),
// warp tile 64x64 (4 m-frags x 8 n-frags). 3-stage cp.async ring.
// All GEMM inputs are PRE-ROUNDED to tf32 bit patterns in gmem, so the
// mma fragment path is raw LDS -> mma (no cvt in the hot loop).
// ---------------------------------------------------------------------------
#define STG_WORDS (2 * 128 * 36)                 // words per stage
#define GEMM_SMEM_BYTES (3 * STG_WORDS * 4)      // 110592

template<int AMODE>
__device__ __forceinline__ void stage_cp(uint32_t sbase, const float* __restrict__ Ag,
                                         int lda, const float* __restrict__ Bg,
                                         int m0, int n0, int kt, int tid) {
    if (AMODE == 0) {
        #pragma unroll
        for (int j = 0; j < 8; j++) {
            int id = tid + 128 * j;
            int kk = id >> 5, mc = (id & 31) * 4;
            cp16(sbase + (kk * 136 + mc) * 4,
                 Ag + (size_t)(kt + kk) * lda + m0 + mc);
        }
    } else {
        #pragma unroll
        for (int j = 0; j < 8; j++) {
            int k4 = tid & 7, mm = (tid >> 3) + 16 * j;
            cp16(sbase + (mm * 36 + 4 * k4) * 4,
                 Ag + (size_t)(m0 + mm) * lda + kt + 4 * k4);
        }
    }
    #pragma unroll
    for (int j = 0; j < 8; j++) {
        int k4 = tid & 7, nn = (tid >> 3) + 16 * j;
        cp16(sbase + (128 * 36 + nn * 36 + 4 * k4) * 4,
             Bg + (size_t)(n0 + nn) * C_ + kt + 4 * k4);
    }
    asm volatile("cp.async.commit_group;" ::: "memory");
}

template<int AMODE>
__device__ __forceinline__ void gemm_core(const float* __restrict__ Ag, int lda,
                                          const float* __restrict__ Bg,
                                          int m0, int n0, int tid,
                                          uint32_t* sm, float acc[4][8][4]) {
    int lane = tid & 31, g = lane >> 2, t4 = lane & 3;
    int warp = tid >> 5, wm = warp & 1, wn = warp >> 1;
    uint32_t sb = (uint32_t)__cvta_generic_to_shared(sm);

    stage_cp<AMODE>(sb,                 Ag, lda, Bg, m0, n0, 0,  tid);
    stage_cp<AMODE>(sb + STG_WORDS * 4, Ag, lda, Bg, m0, n0, 32, tid);

    #pragma unroll 1
    for (int kc = 0; kc < 12; kc++) {
        if (kc == 11) asm volatile("cp.async.wait_group 0;" ::: "memory");
        else          asm volatile("cp.async.wait_group 1;" ::: "memory");
        __syncthreads();
        if (kc + 2 < 12)
            stage_cp<AMODE>(sb + ((kc + 2) % 3) * STG_WORDS * 4,
                            Ag, lda, Bg, m0, n0, (kc + 2) * 32, tid);

        const uint32_t* sA = sm + (kc % 3) * STG_WORDS;
        const uint32_t* sB = sA + 128 * 36;
        #pragma unroll
        for (int k8 = 0; k8 < 4; k8++) {
            uint32_t a[4][4], bq[8][2];
            #pragma unroll
            for (int mf = 0; mf < 4; mf++) {
                int m = wm * 64 + mf * 16 + g;
                if (AMODE == 0) {
                    a[mf][0] = sA[(k8 * 8 + t4) * 136 + m];
                    a[mf][1] = sA[(k8 * 8 + t4) * 136 + m + 8];
                    a[mf][2] = sA[(k8 * 8 + t4 + 4) * 136 + m];
                    a[mf][3] = sA[(k8 * 8 + t4 + 4) * 136 + m + 8];
                } else {
                    const uint32_t* pa = sA + m * 36 + k8 * 8 + t4;
                    a[mf][0] = pa[0];
                    a[mf][1] = pa[8 * 36];
                    a[mf][2] = pa[4];
                    a[mf][3] = pa[8 * 36 + 4];
                }
            }
            #pragma unroll
            for (int nf = 0; nf < 8; nf++) {
                const uint32_t* pb = sB + (wn * 64 + nf * 8 + g) * 36 + k8 * 8 + t4;
                bq[nf][0] = pb[0];
                bq[nf][1] = pb[4];
            }
            #pragma unroll
            for (int mf = 0; mf < 4; mf++)
                #pragma unroll
                for (int nf = 0; nf < 8; nf++)
                    mma8(acc[mf][nf], a[mf][0], a[mf][1], a[mf][2], a[mf][3],
                         bq[nf][0], bq[nf][1]);
        }
        __syncthreads();
    }
}

// Chunked NCHW epilogue: 4 chunks of 32 channels, staged [ch][m] stride 132.
template<typename F>
__device__ __forceinline__ void epi_nchw(uint32_t* sm, float acc[4][8][4],
                                         int tid, float* dst, int strideM,
                                         int m0, int n0, F f) {
    float* sC = (float*)sm;
    int lane = tid & 31, g = lane >> 2, t4 = lane & 3;
    int warp = tid >> 5, wm = warp & 1, wn = warp >> 1;
    #pragma unroll
    for (int c = 0; c < 4; c++) {
        if (wn == (c >> 1)) {
            int nf0 = 4 * (c & 1);
            #pragma unroll
            for (int mf = 0; mf < 4; mf++) {
                int r = wm * 64 + mf * 16 + g;
                #pragma unroll
                for (int nfl = 0; nfl < 4; nfl++) {
                    int nf = nf0 + nfl;
                    int chl = nfl * 8 + 2 * t4;
                    sC[chl * 132 + r]           = acc[mf][nf][0];
                    sC[(chl + 1) * 132 + r]     = acc[mf][nf][1];
                    sC[chl * 132 + r + 8]       = acc[mf][nf][2];
                    sC[(chl + 1) * 132 + r + 8] = acc[mf][nf][3];
                }
            }
        }
        __syncthreads();
        for (int i = tid; i < 4096; i += 128) {
            int ch = i >> 7, mm = i & 127;
            int gc = n0 + 32 * c + ch;
            dst[(size_t)gc * strideM + m0 + mm] = f(sC[ch * 132 + mm], gc);
        }
        __syncthreads();
    }
}

// ---------------------------------------------------------------------------
// lin GEMM: xz[m][d] = sum_c xdw[c][m]*lin_w[d][c] + lin_b[d]
// by 0..2 -> xs (NCHW); by 3..5 -> z (token-major)
// ---------------------------------------------------------------------------
struct AddBias {
    const float* b;
    __device__ float operator()(float v, int ch) const { return v + b[ch]; }
};

__global__ void __launch_bounds__(128, 2) k_lin_mma(const float* __restrict__ lb) {
    extern __shared__ __align__(16) uint32_t sm[];
    int tid = threadIdx.x;
    int b = blockIdx.z, m0 = blockIdx.x * 128, n0 = blockIdx.y * 128;
    float acc[4][8][4];
    #pragma unroll
    for (int i = 0; i < 4; i++)
        #pragma unroll
        for (int j = 0; j < 8; j++)
            #pragma unroll
            for (int k = 0; k < 4; k++) acc[i][j][k] = 0.0f;

    gemm_core<0>(g_buf0 + (size_t)b * C_ * HW_, HW_, g_lwR, m0, n0, tid, sm, acc);

    if (n0 < C_) {
        epi_nchw(sm, acc, tid, g_buf1 + (size_t)b * C_ * HW_, HW_, m0, n0,
                 AddBias{lb});
    } else {
        // z half -> token-major [m][C_], 2 chunks of 64 rows (by wm)
        float* sC = (float*)sm;
        int lane = tid & 31, g = lane >> 2, t4 = lane & 3;
        int warp = tid >> 5, wm = warp & 1, wn = warp >> 1;
        float* zb = g_z + (size_t)b * HW_ * C_;
        int zoff = n0 - C_;
        #pragma unroll
        for (int j = 0; j < 2; j++) {
            if (wm == j) {
                #pragma unroll
                for (int mf = 0; mf < 4; mf++) {
                    int rl = mf * 16 + g;
                    #pragma unroll
                    for (int nf = 0; nf < 8; nf++) {
                        int cc = wn * 64 + nf * 8 + 2 * t4;
                        *(float2*)(sC + rl * 132 + cc) =
                            make_float2(acc[mf][nf][0], acc[mf][nf][1]);
                        *(float2*)(sC + (rl + 8) * 132 + cc) =
                            make_float2(acc[mf][nf][2], acc[mf][nf][3]);
                    }
                }
            }
            __syncthreads();
            for (int i = tid; i < 2048; i += 128) {
                int row = i >> 5, q = i & 31;
                float4 v = *(float4*)(sC + row * 132 + 4 * q);
                float4 bb = *(const float4*)(lb + C_ + zoff + 4 * q);
                v.x += bb.x; v.y += bb.y; v.z += bb.z; v.w += bb.w;
                *(float4*)(zb + (size_t)(m0 + 64 * j + row) * C_ + zoff + 4 * q) = v;
            }
            __syncthreads();
        }
    }
}

// ---------------------------------------------------------------------------
// gate GEMM: t = relu(fe @ tok_w^T + tok_b); gate = cos(c*t)+sin(c*t)*(1+.5a)/c
// ---------------------------------------------------------------------------
struct GateXform {
    const float* tb;
    float c0, s1;
    __device__ float operator()(float v, int ch) const {
        float t = fmaxf(v + tb[ch], 0.0f);
        float ct = c0 * t;
        return cosf(ct) + sinf(ct) * s1;
    }
};

__global__ void __launch_bounds__(128, 2) k_gate_mma(const float* __restrict__ tb,
                                                     const float* __restrict__ cp,
                                                     const float* __restrict__ ap) {
    extern __shared__ __align__(16) uint32_t sm[];
    int tid = threadIdx.x;
    int m0 = blockIdx.x * 128, n0 = blockIdx.y * 128;
    float acc[4][8][4];
    #pragma unroll
    for (int i = 0; i < 4; i++)
        #pragma unroll
        for (int j = 0; j < 8; j++)
            #pragma unroll
            for (int k = 0; k < 4; k++) acc[i][j][k] = 0.0f;

    gemm_core<1>(g_feR, C_, g_twR, m0, n0, tid, sm, acc);

    float c0 = cp[0];
    float s1 = (1.0f + 0.5f * ap[0]) / c0;
    epi_nchw(sm, acc, tid, g_gate, HW_, m0, n0, GateXform{tb, c0, s1});
}

// ---------------------------------------------------------------------------
// out GEMM: out[d][m] = sum_c y[m][c]*out_w[d][c] + out_b[d]
// ---------------------------------------------------------------------------
__global__ void __launch_bounds__(128, 2) k_out_mma(const float* __restrict__ ob,
                                                    float* __restrict__ out) {
    extern __shared__ __align__(16) uint32_t sm[];
    int tid = threadIdx.x;
    int b = blockIdx.z, m0 = blockIdx.x * 128, n0 = blockIdx.y * 128;
    float acc[4][8][4];
    #pragma unroll
    for (int i = 0; i < 4; i++)
        #pragma unroll
        for (int j = 0; j < 8; j++)
            #pragma unroll
            for (int k = 0; k < 4; k++) acc[i][j][k] = 0.0f;

    gemm_core<1>(g_buf1 + (size_t)b * HW_ * C_, C_, g_owR, m0, n0, tid, sm, acc);

    epi_nchw(sm, acc, tid, out + (size_t)b * C_ * HW_, HW_, m0, n0, AddBias{ob});
}

// ===========================================================================
// Fused DCT -> gate -> iDCT per (b,c) image, tf32 mma (one image per block,
// 58 KB smem, 8 warps, warp tile 16x32).
// ---------------------------------------------------------------------------
#define DS 76
#define DTILE (64 * DS)
#define DCT_SMEM_BYTES (3 * DTILE * 4)

__device__ __forceinline__ void dct_mm(const uint32_t* __restrict__ pA,
                                       const uint32_t* __restrict__ pB,
                                       float acc[4][4], int r, int nb,
                                       int g, int t4) {
    #pragma unroll
    for (int nf = 0; nf < 4; nf++)
        #pragma unroll
        for (int j = 0; j < 4; j++) acc[nf][j] = 0.0f;
    #pragma unroll
    for (int k8 = 0; k8 < 8; k8++) {
        uint32_t a0 = pA[r * DS + k8 * 8 + t4];
        uint32_t a1 = pA[(r + 8) * DS + k8 * 8 + t4];
        uint32_t a2 = pA[r * DS + k8 * 8 + t4 + 4];
        uint32_t a3 = pA[(r + 8) * DS + k8 * 8 + t4 + 4];
        #pragma unroll
        for (int nf = 0; nf < 4; nf++) {
            int n = nb + nf * 8 + g;
            uint32_t b0 = pB[(k8 * 8 + t4) * DS + n];
            uint32_t b1 = pB[(k8 * 8 + t4 + 4) * DS + n];
            mma8(acc[nf], a0, a1, a2, a3, b0, b1);
        }
    }
}

__global__ void __launch_bounds__(256) k_dct_mma() {
    extern __shared__ uint32_t dsm[];
    uint32_t* tW = dsm;
    uint32_t* tA = dsm + DTILE;
    uint32_t* tB = dsm + 2 * DTILE;
    int bc = blockIdx.x;
    int c = bc % C_;
    int tid = threadIdx.x;
    const float* xim = g_buf1 + (size_t)bc * HW_;
    for (int i = tid; i < 4096; i += 256) {
        int h = i >> 6, w = i & 63;
        tW[h * DS + w] = f2tf(g_W[i]);
        tA[h * DS + w] = f2tf(xim[i]);
    }
    __syncthreads();

    int lane = tid & 31, g = lane >> 2, t4 = lane & 3;
    int warp = tid >> 5, wm = warp & 3, wn = warp >> 2;
    int r = wm * 16 + g, nb = wn * 32;
    float acc[4][4];

    // mm1: M1[n][w] = sum_h W[n][h] X[h][w]  -> store transposed tB[w][n]
    dct_mm(tW, tA, acc, r, nb, g, t4);
    #pragma unroll
    for (int nf = 0; nf < 4; nf++) {
        int cc = nb + nf * 8 + 2 * t4;
        tB[cc * DS + r]           = f2tf(acc[nf][0]);
        tB[(cc + 1) * DS + r]     = f2tf(acc[nf][1]);
        tB[cc * DS + r + 8]       = f2tf(acc[nf][2]);
        tB[(cc + 1) * DS + r + 8] = f2tf(acc[nf][3]);
    }
    __syncthreads();

    // mm2: XdT[k][n] = sum_w W[k][w] M1T[w][n]; gate; store tA[k][n]
    dct_mm(tW, tB, acc, r, nb, g, t4);
    {
        const float* gp = g_gate + (size_t)c * HW_;
        #pragma unroll
        for (int nf = 0; nf < 4; nf++) {
            int cc = nb + nf * 8 + 2 * t4;
            float g0 = gp[cc * 64 + r];
            float g1 = gp[(cc + 1) * 64 + r];
            float g2 = gp[cc * 64 + r + 8];
            float g3 = gp[(cc + 1) * 64 + r + 8];
            tA[r * DS + cc]           = f2tf(acc[nf][0] * g0);
            tA[r * DS + cc + 1]       = f2tf(acc[nf][1] * g1);
            tA[(r + 8) * DS + cc]     = f2tf(acc[nf][2] * g2);
            tA[(r + 8) * DS + cc + 1] = f2tf(acc[nf][3] * g3);
        }
    }
    __syncthreads();

    // mm3: M2T[k][h] = sum_n F[k][n] W[n][h] -> store transposed tB[h][k]
    dct_mm(tA, tW, acc, r, nb, g, t4);
    #pragma unroll
    for (int nf = 0; nf < 4; nf++) {
        int cc = nb + nf * 8 + 2 * t4;
        tB[cc * DS + r]           = f2tf(acc[nf][0]);
        tB[(cc + 1) * DS + r]     = f2tf(acc[nf][1]);
        tB[cc * DS + r + 8]       = f2tf(acc[nf][2]);
        tB[(cc + 1) * DS + r + 8] = f2tf(acc[nf][3]);
    }
    __syncthreads();

    // mm4: xi[h][w] = sum_k M2T[k][h] W[k][w] -> gmem
    dct_mm(tB, tW, acc, r, nb, g, t4);
    float* xo = g_buf0 + (size_t)bc * HW_;
    #pragma unroll
    for (int nf = 0; nf < 4; nf++) {
        int cc = nb + nf * 8 + 2 * t4;
        *(float2*)(xo + r * 64 + cc)       = make_float2(acc[nf][0], acc[nf][1]);
        *(float2*)(xo + (r + 8) * 64 + cc) = make_float2(acc[nf][2], acc[nf][3]);
    }
}

// ---------------------------------------------------------------------------
// LayerNorm over channels + SiLU(z) gate. 16 tokens per block of 128 threads.
// Output y pre-rounded to tf32 bits (consumed only by out GEMM).
// ---------------------------------------------------------------------------
__global__ void k_ln(const float* __restrict__ lng, const float* __restrict__ lnb) {
    __shared__ float s[C_ * 17];
    int tid = threadIdx.x;
    int mglob = blockIdx.x * 16;
    int b = mglob >> 12;
    int mloc = mglob & 4095;
    const float* xi = g_buf0 + (size_t)b * C_ * HW_ + mloc;
    for (int i = tid; i < C_ * 16; i += 128) {
        int cc = i >> 4, t = i & 15;
        s[cc * 17 + t] = xi[(size_t)cc * HW_ + t];
    }
    __syncthreads();
    int tk = tid >> 3, g = tid & 7;
    float sum = 0.0f, ss = 0.0f;
    #pragma unroll 8
    for (int ii = 0; ii < 48; ii++) {
        int cc = g + ii * 8;
        float v = s[cc * 17 + tk];
        sum += v; ss += v * v;
    }
    #pragma unroll
    for (int off = 4; off; off >>= 1) {
        sum += __shfl_down_sync(0xffffffffu, sum, off);
        ss  += __shfl_down_sync(0xffffffffu, ss,  off);
    }
    int lane = tid & 31;
    int src = lane & ~7;
    sum = __shfl_sync(0xffffffffu, sum, src);
    ss  = __shfl_sync(0xffffffffu, ss,  src);
    float mu = sum * (1.0f / 384.0f);
    float var = ss * (1.0f / 384.0f) - mu * mu;
    float rstd = rsqrtf(fmaxf(var, 0.0f) + 1e-5f);

    int mt = mloc + tk;
    const float* zp = g_z + ((size_t)b * HW_ + mt) * C_;
    float* yp = g_buf1 + ((size_t)b * HW_ + mt) * C_;
    #pragma unroll 4
    for (int ii = 0; ii < 12; ii++) {
        int c0 = g * 48 + ii * 4;
        float4 zv = *(const float4*)(zp + c0);
        float4 gg = *(const float4*)(lng + c0);
        float4 bb = *(const float4*)(lnb + c0);
        float y0 = (s[(c0 + 0) * 17 + tk] - mu) * rstd * gg.x + bb.x;
        float y1 = (s[(c0 + 1) * 17 + tk] - mu) * rstd * gg.y + bb.y;
        float y2 = (s[(c0 + 2) * 17 + tk] - mu) * rstd * gg.z + bb.z;
        float y3 = (s[(c0 + 3) * 17 + tk] - mu) * rstd * gg.w + bb.w;
        y0 *= zv.x / (1.0f + __expf(-zv.x));
        y1 *= zv.y / (1.0f + __expf(-zv.y));
        y2 *= zv.z / (1.0f + __expf(-zv.z));
        y3 *= zv.w / (1.0f + __expf(-zv.w));
        *(float4*)(yp + c0) = make_float4(f2tf_f(y0), f2tf_f(y1),
                                          f2tf_f(y2), f2tf_f(y3));
    }
}

// ---------------------------------------------------------------------------
extern "C" void kernel_launch(void* const* d_in, const int* in_sizes, int n_in,
                              void* d_out, int out_size) {
    const float* x     = (const float*)d_in[0];
    const float* fe    = (const float*)d_in[1];
    const float* dw_w  = (const float*)d_in[2];
    const float* dw_b  = (const float*)d_in[3];
    const float* lin_w = (const float*)d_in[4];
    const float* lin_b = (const float*)d_in[5];
    const float* tok_w = (const float*)d_in[6];
    const float* tok_b = (const float*)d_in[7];
    const float* cc    = (const float*)d_in[8];
    const float* alpha = (const float*)d_in[9];
    const float* ln_g  = (const float*)d_in[10];
    const float* ln_b  = (const float*)d_in[11];
    const float* out_w = (const float*)d_in[12];
    const float* out_b = (const float*)d_in[13];
    float* out = (float*)d_out;

    cudaFuncSetAttribute(k_dct_mma, cudaFuncAttributeMaxDynamicSharedMemorySize,
                         DCT_SMEM_BYTES);
    cudaFuncSetAttribute(k_lin_mma, cudaFuncAttributeMaxDynamicSharedMemorySize,
                         GEMM_SMEM_BYTES);
    cudaFuncSetAttribute(k_gate_mma, cudaFuncAttributeMaxDynamicSharedMemorySize,
                         GEMM_SMEM_BYTES);
    cudaFuncSetAttribute(k_out_mma, cudaFuncAttributeMaxDynamicSharedMemorySize,
                         GEMM_SMEM_BYTES);

    // pre-round GEMM inputs to tf32 bit patterns
    k_round<<<(HW_ * C_ / 4 + 255) / 256, 256>>>(fe, 0, HW_ * C_ / 4);
    k_round<<<(2 * C_ * C_ / 4 + 255) / 256, 256>>>(lin_w, 1, 2 * C_ * C_ / 4);
    k_round<<<(C_ * C_ / 4 + 255) / 256, 256>>>(tok_w, 2, C_ * C_ / 4);
    k_round<<<(C_ * C_ / 4 + 255) / 256, 256>>>(out_w, 3, C_ * C_ / 4);

    k_dct_basis<<<64, 64>>>();
    k_dwconv<<<B_ * C_, 256>>>(x, dw_w, dw_b);
    k_gate_mma<<<dim3(32, 3), 128, GEMM_SMEM_BYTES>>>(tok_b, cc, alpha);
    k_lin_mma<<<dim3(32, 6, B_), 128, GEMM_SMEM_BYTES>>>(lin_b);
    k_dct_mma<<<B_ * C_, 256, DCT_SMEM_BYTES>>>();
    k_ln<<<(B_ * HW_) / 16, 128>>>(ln_g, ln_b);
    k_out_mma<<<dim3(32, 3, B_), 128, GEMM_SMEM_BYTES>>>(out_b, out);
}

// round 13
// speedup vs baseline: 1.6408x; 1.1109x over previous
#include <cuda_runtime.h>
#include <math.h>
#include <stdint.h>

#define B_ 8
#define C_ 384
#define HW_ 4096

// Scratch (device globals — no runtime allocation)
__device__ float g_buf0[B_ * C_ * HW_];   // xdw (tf32-rounded), later xi
__device__ float g_buf1[B_ * C_ * HW_];   // xs (tf32-rounded), later y (tf32-rounded)
__device__ float g_z[B_ * HW_ * C_];      // z token-major (full f32)
__device__ float g_gate[C_ * HW_];        // spectral gate [c][n*64+k]
__device__ float g_W[64 * 64];            // DCT-II basis, tf32-rounded
// pre-rounded (tf32-bit) copies of GEMM inputs
__device__ float g_feR[HW_ * C_];
__device__ float g_lwR[2 * C_ * C_];
__device__ float g_twR[C_ * C_];
__device__ float g_owR[C_ * C_];

// ---------------------------------------------------------------------------
// helpers
// ---------------------------------------------------------------------------
__device__ __forceinline__ uint32_t f2tf(float f) {
    uint32_t u;
    asm("cvt.rna.tf32.f32 %0, %1;" : "=r"(u) : "f"(f));
    return u;
}
__device__ __forceinline__ float f2tf_f(float f) {
    return __uint_as_float(f2tf(f));
}

__device__ __forceinline__ void mma8(float* c, uint32_t a0, uint32_t a1,
                                     uint32_t a2, uint32_t a3,
                                     uint32_t b0, uint32_t b1) {
    asm volatile(
        "mma.sync.aligned.m16n8k8.row.col.f32.tf32.tf32.f32 "
        "{%0,%1,%2,%3}, {%4,%5,%6,%7}, {%8,%9}, {%0,%1,%2,%3};"
        : "+f"(c[0]), "+f"(c[1]), "+f"(c[2]), "+f"(c[3])
        : "r"(a0), "r"(a1), "r"(a2), "r"(a3), "r"(b0), "r"(b1));
}

__device__ __forceinline__ void cp16(uint32_t dst_smem, const void* src) {
    asm volatile("cp.async.cg.shared.global [%0], [%1], 16;"
                 :: "r"(dst_smem), "l"(src));
}

// ---------------------------------------------------------------------------
// Pre-round inputs to tf32 bit patterns (idempotent with mma rounding).
// which: 0 = fe, 1 = lin_w, 2 = tok_w, 3 = out_w
// ---------------------------------------------------------------------------
__global__ void k_round(const float* __restrict__ src, int which, int n4) {
    int i = blockIdx.x * blockDim.x + threadIdx.x;
    if (i >= n4) return;
    float* dst = which == 0 ? g_feR : which == 1 ? g_lwR
               : which == 2 ? g_twR : g_owR;
    float4 v = ((const float4*)src)[i];
    v.x = f2tf_f(v.x); v.y = f2tf_f(v.y);
    v.z = f2tf_f(v.z); v.w = f2tf_f(v.w);
    ((float4*)dst)[i] = v;
}

// ---------------------------------------------------------------------------
// DCT basis (stored tf32-pre-rounded; consumed only as mma operand)
// ---------------------------------------------------------------------------
__global__ void k_dct_basis() {
    int n = blockIdx.x, x = threadIdx.x;
    float v = cosf((float)n * ((float)x + 0.5f) * (3.14159265358979323846f / 64.0f))
              * 0.17677669529663687f;
    if (n == 0) v *= 0.70710678118654752f;
    g_W[n * 64 + x] = f2tf_f(v);
}

// ---------------------------------------------------------------------------
// Depthwise 3x3 conv (SAME) + bias. One block per (b,c) image.
// smem [66][72]: image (gh,gw) -> s[(gh+1)*72 + gw + 4] (interior 16B-aligned).
// Interior loaded as float4 (coalesced); halo zeroed explicitly.
// Output tf32-pre-rounded, float4 stores.
// ---------------------------------------------------------------------------
__global__ void k_dwconv(const float* __restrict__ x,
                         const float* __restrict__ w,
                         const float* __restrict__ bias) {
    __shared__ float s[66 * 72];
    int bc = blockIdx.x;
    int tid = threadIdx.x;
    const float4* xim4 = (const float4*)(x + (size_t)bc * HW_);

    // zero halo: rows 0 and 65 (cols 3..68), cols 3 and 68 (rows 1..64)
    if (tid < 72) { s[tid] = 0.0f; s[65 * 72 + tid] = 0.0f; }
    if (tid < 64) { s[(tid + 1) * 72 + 3] = 0.0f; s[(tid + 1) * 72 + 68] = 0.0f; }

    // interior: 1024 float4
    #pragma unroll
    for (int i = tid; i < 1024; i += 256) {
        int h = i >> 4, w4 = (i & 15) * 4;
        *(float4*)(s + (h + 1) * 72 + 4 + w4) = xim4[i];
    }

    int c = bc % C_;
    const float* wp = w + c * 9;
    float w0 = wp[0], w1 = wp[1], w2 = wp[2];
    float w3 = wp[3], w4_ = wp[4], w5 = wp[5];
    float w6 = wp[6], w7 = wp[7], w8 = wp[8];
    float bv = bias[c];
    __syncthreads();

    float* outp = g_buf0 + (size_t)bc * HW_;
    #pragma unroll
    for (int i = tid; i < 1024; i += 256) {
        int h = i >> 4, ww = (i & 15) * 4;
        const float* r0 = s + h * 72 + ww + 3;          // (h-1, w-1)
        const float* r1 = r0 + 72;
        const float* r2 = r0 + 144;
        float a0 = r0[0], a1 = r0[1], a2 = r0[2], a3 = r0[3], a4 = r0[4], a5 = r0[5];
        float b0 = r1[0], b1 = r1[1], b2 = r1[2], b3 = r1[3], b4 = r1[4], b5 = r1[5];
        float c0 = r2[0], c1 = r2[1], c2 = r2[2], c3 = r2[3], c4 = r2[4], c5 = r2[5];
        float o0 = bv, o1 = bv, o2 = bv, o3 = bv;
        o0 = fmaf(a0, w0, o0); o0 = fmaf(a1, w1, o0); o0 = fmaf(a2, w2, o0);
        o0 = fmaf(b0, w3, o0); o0 = fmaf(b1, w4_, o0); o0 = fmaf(b2, w5, o0);
        o0 = fmaf(c0, w6, o0); o0 = fmaf(c1, w7, o0); o0 = fmaf(c2, w8, o0);
        o1 = fmaf(a1, w0, o1); o1 = fmaf(a2, w1, o1); o1 = fmaf(a3, w2, o1);
        o1 = fmaf(b1, w3, o1); o1 = fmaf(b2, w4_, o1); o1 = fmaf(b3, w5, o1);
        o1 = fmaf(c1, w6, o1); o1 = fmaf(c2, w7, o1); o1 = fmaf(c3, w8, o1);
        o2 = fmaf(a2, w0, o2); o2 = fmaf(a3, w1, o2); o2 = fmaf(a4, w2, o2);
        o2 = fmaf(b2, w3, o2); o2 = fmaf(b3, w4_, o2); o2 = fmaf(b4, w5, o2);
        o2 = fmaf(c2, w6, o2); o2 = fmaf(c3, w7, o2); o2 = fmaf(c4, w8, o2);
        o3 = fmaf(a3, w0, o3); o3 = fmaf(a4, w1, o3); o3 = fmaf(a5, w2, o3);
        o3 = fmaf(b3, w3, o3); o3 = fmaf(b4, w4_, o3); o3 = fmaf(b5, w5, o3);
        o3 = fmaf(c3, w6, o3); o3 = fmaf(c4, w7, o3); o3 = fmaf(c5, w8, o3);
        *(float4*)(outp + i * 4) = make_float4(f2tf_f(o0), f2tf_f(o1),
                                               f2tf_f(o2), f2tf_f(o3));
    }
}

// ===========================================================================
// GEMM core v6: block 128(M) x 128(N), 128 threads = 4 warps (2m x 2n),
// warp tile 64x64. 3-stage cp.async ring, ONE sync per chunk (the trailing
// sync is redundant: stage target (kc+2)%3 never aliases the read buffer,
// and the next chunk's collective top-sync bounds warp skew).
// All GEMM inputs pre-rounded tf32 -> raw LDS -> mma.
// ---------------------------------------------------------------------------
#define STG_WORDS (2 * 128 * 36)                 // words per stage
#define GEMM_SMEM_BYTES (3 * STG_WORDS * 4)      // 110592

template<int AMODE>
__device__ __forceinline__ void stage_cp(uint32_t sbase, const float* __restrict__ Ag,
                                         int lda, const float* __restrict__ Bg,
                                         int m0, int n0, int kt, int tid) {
    if (AMODE == 0) {
        #pragma unroll
        for (int j = 0; j < 8; j++) {
            int id = tid + 128 * j;
            int kk = id >> 5, mc = (id & 31) * 4;
            cp16(sbase + (kk * 136 + mc) * 4,
                 Ag + (size_t)(kt + kk) * lda + m0 + mc);
        }
    } else {
        #pragma unroll
        for (int j = 0; j < 8; j++) {
            int k4 = tid & 7, mm = (tid >> 3) + 16 * j;
            cp16(sbase + (mm * 36 + 4 * k4) * 4,
                 Ag + (size_t)(m0 + mm) * lda + kt + 4 * k4);
        }
    }
    #pragma unroll
    for (int j = 0; j < 8; j++) {
        int k4 = tid & 7, nn = (tid >> 3) + 16 * j;
        cp16(sbase + (128 * 36 + nn * 36 + 4 * k4) * 4,
             Bg + (size_t)(n0 + nn) * C_ + kt + 4 * k4);
    }
    asm volatile("cp.async.commit_group;" ::: "memory");
}

template<int AMODE>
__device__ __forceinline__ void gemm_core(const float* __restrict__ Ag, int lda,
                                          const float* __restrict__ Bg,
                                          int m0, int n0, int tid,
                                          uint32_t* sm, float acc[4][8][4]) {
    int lane = tid & 31, g = lane >> 2, t4 = lane & 3;
    int warp = tid >> 5, wm = warp & 1, wn = warp >> 1;
    uint32_t sb = (uint32_t)__cvta_generic_to_shared(sm);

    stage_cp<AMODE>(sb,                 Ag, lda, Bg, m0, n0, 0,  tid);
    stage_cp<AMODE>(sb + STG_WORDS * 4, Ag, lda, Bg, m0, n0, 32, tid);

    #pragma unroll 1
    for (int kc = 0; kc < 12; kc++) {
        if (kc == 11) asm volatile("cp.async.wait_group 0;" ::: "memory");
        else          asm volatile("cp.async.wait_group 1;" ::: "memory");
        __syncthreads();
        if (kc + 2 < 12)
            stage_cp<AMODE>(sb + ((kc + 2) % 3) * STG_WORDS * 4,
                            Ag, lda, Bg, m0, n0, (kc + 2) * 32, tid);

        const uint32_t* sA = sm + (kc % 3) * STG_WORDS;
        const uint32_t* sB = sA + 128 * 36;
        #pragma unroll
        for (int k8 = 0; k8 < 4; k8++) {
            uint32_t a[4][4], bq[8][2];
            #pragma unroll
            for (int mf = 0; mf < 4; mf++) {
                int m = wm * 64 + mf * 16 + g;
                if (AMODE == 0) {
                    a[mf][0] = sA[(k8 * 8 + t4) * 136 + m];
                    a[mf][1] = sA[(k8 * 8 + t4) * 136 + m + 8];
                    a[mf][2] = sA[(k8 * 8 + t4 + 4) * 136 + m];
                    a[mf][3] = sA[(k8 * 8 + t4 + 4) * 136 + m + 8];
                } else {
                    const uint32_t* pa = sA + m * 36 + k8 * 8 + t4;
                    a[mf][0] = pa[0];
                    a[mf][1] = pa[8 * 36];
                    a[mf][2] = pa[4];
                    a[mf][3] = pa[8 * 36 + 4];
                }
            }
            #pragma unroll
            for (int nf = 0; nf < 8; nf++) {
                const uint32_t* pb = sB + (wn * 64 + nf * 8 + g) * 36 + k8 * 8 + t4;
                bq[nf][0] = pb[0];
                bq[nf][1] = pb[4];
            }
            #pragma unroll
            for (int mf = 0; mf < 4; mf++)
                #pragma unroll
                for (int nf = 0; nf < 8; nf++)
                    mma8(acc[mf][nf], a[mf][0], a[mf][1], a[mf][2], a[mf][3],
                         bq[nf][0], bq[nf][1]);
        }
        // no trailing sync: next chunk's top sync bounds skew
    }
}

// Chunked NCHW epilogue: 4 chunks of 32 channels, staged [ch][m] stride 132.
// Entry sync required (gemm_core no longer ends with one).
template<typename F>
__device__ __forceinline__ void epi_nchw(uint32_t* sm, float acc[4][8][4],
                                         int tid, float* dst, int strideM,
                                         int m0, int n0, F f) {
    float* sC = (float*)sm;
    int lane = tid & 31, g = lane >> 2, t4 = lane & 3;
    int warp = tid >> 5, wm = warp & 1, wn = warp >> 1;
    __syncthreads();
    #pragma unroll
    for (int c = 0; c < 4; c++) {
        if (wn == (c >> 1)) {
            int nf0 = 4 * (c & 1);
            #pragma unroll
            for (int mf = 0; mf < 4; mf++) {
                int r = wm * 64 + mf * 16 + g;
                #pragma unroll
                for (int nfl = 0; nfl < 4; nfl++) {
                    int nf = nf0 + nfl;
                    int chl = nfl * 8 + 2 * t4;
                    sC[chl * 132 + r]           = acc[mf][nf][0];
                    sC[(chl + 1) * 132 + r]     = acc[mf][nf][1];
                    sC[chl * 132 + r + 8]       = acc[mf][nf][2];
                    sC[(chl + 1) * 132 + r + 8] = acc[mf][nf][3];
                }
            }
        }
        __syncthreads();
        for (int i = tid; i < 4096; i += 128) {
            int ch = i >> 7, mm = i & 127;
            int gc = n0 + 32 * c + ch;
            dst[(size_t)gc * strideM + m0 + mm] = f(sC[ch * 132 + mm], gc);
        }
        __syncthreads();
    }
}

// ---------------------------------------------------------------------------
// lin GEMM: xz[m][d] = sum_c xdw[c][m]*lin_w[d][c] + lin_b[d]
// by 0..2 -> xs (NCHW, tf32-pre-rounded for DCT); by 3..5 -> z (token-major)
// ---------------------------------------------------------------------------
struct AddBias {
    const float* b;
    __device__ float operator()(float v, int ch) const { return v + b[ch]; }
};
struct AddBiasRound {
    const float* b;
    __device__ float operator()(float v, int ch) const { return f2tf_f(v + b[ch]); }
};

__global__ void __launch_bounds__(128, 2) k_lin_mma(const float* __restrict__ lb) {
    extern __shared__ __align__(16) uint32_t sm[];
    int tid = threadIdx.x;
    int b = blockIdx.z, m0 = blockIdx.x * 128, n0 = blockIdx.y * 128;
    float acc[4][8][4];
    #pragma unroll
    for (int i = 0; i < 4; i++)
        #pragma unroll
        for (int j = 0; j < 8; j++)
            #pragma unroll
            for (int k = 0; k < 4; k++) acc[i][j][k] = 0.0f;

    gemm_core<0>(g_buf0 + (size_t)b * C_ * HW_, HW_, g_lwR, m0, n0, tid, sm, acc);

    if (n0 < C_) {
        epi_nchw(sm, acc, tid, g_buf1 + (size_t)b * C_ * HW_, HW_, m0, n0,
                 AddBiasRound{lb});
    } else {
        // z half -> token-major [m][C_], 2 chunks of 64 rows (by wm)
        float* sC = (float*)sm;
        int lane = tid & 31, g = lane >> 2, t4 = lane & 3;
        int warp = tid >> 5, wm = warp & 1, wn = warp >> 1;
        float* zb = g_z + (size_t)b * HW_ * C_;
        int zoff = n0 - C_;
        __syncthreads();
        #pragma unroll
        for (int j = 0; j < 2; j++) {
            if (wm == j) {
                #pragma unroll
                for (int mf = 0; mf < 4; mf++) {
                    int rl = mf * 16 + g;
                    #pragma unroll
                    for (int nf = 0; nf < 8; nf++) {
                        int cc = wn * 64 + nf * 8 + 2 * t4;
                        *(float2*)(sC + rl * 132 + cc) =
                            make_float2(acc[mf][nf][0], acc[mf][nf][1]);
                        *(float2*)(sC + (rl + 8) * 132 + cc) =
                            make_float2(acc[mf][nf][2], acc[mf][nf][3]);
                    }
                }
            }
            __syncthreads();
            for (int i = tid; i < 2048; i += 128) {
                int row = i >> 5, q = i & 31;
                float4 v = *(float4*)(sC + row * 132 + 4 * q);
                float4 bb = *(const float4*)(lb + C_ + zoff + 4 * q);
                v.x += bb.x; v.y += bb.y; v.z += bb.z; v.w += bb.w;
                *(float4*)(zb + (size_t)(m0 + 64 * j + row) * C_ + zoff + 4 * q) = v;
            }
            __syncthreads();
        }
    }
}

// ---------------------------------------------------------------------------
// gate GEMM: t = relu(fe @ tok_w^T + tok_b); gate = cos(c*t)+sin(c*t)*(1+.5a)/c
// ---------------------------------------------------------------------------
struct GateXform {
    const float* tb;
    float c0, s1;
    __device__ float operator()(float v, int ch) const {
        float t = fmaxf(v + tb[ch], 0.0f);
        float ct = c0 * t;
        return cosf(ct) + sinf(ct) * s1;
    }
};

__global__ void __launch_bounds__(128, 2) k_gate_mma(const float* __restrict__ tb,
                                                     const float* __restrict__ cp,
                                                     const float* __restrict__ ap) {
    extern __shared__ __align__(16) uint32_t sm[];
    int tid = threadIdx.x;
    int m0 = blockIdx.x * 128, n0 = blockIdx.y * 128;
    float acc[4][8][4];
    #pragma unroll
    for (int i = 0; i < 4; i++)
        #pragma unroll
        for (int j = 0; j < 8; j++)
            #pragma unroll
            for (int k = 0; k < 4; k++) acc[i][j][k] = 0.0f;

    gemm_core<1>(g_feR, C_, g_twR, m0, n0, tid, sm, acc);

    float c0 = cp[0];
    float s1 = (1.0f + 0.5f * ap[0]) / c0;
    epi_nchw(sm, acc, tid, g_gate, HW_, m0, n0, GateXform{tb, c0, s1});
}

// ---------------------------------------------------------------------------
// out GEMM: out[d][m] = sum_c y[m][c]*out_w[d][c] + out_b[d]
// ---------------------------------------------------------------------------
__global__ void __launch_bounds__(128, 2) k_out_mma(const float* __restrict__ ob,
                                                    float* __restrict__ out) {
    extern __shared__ __align__(16) uint32_t sm[];
    int tid = threadIdx.x;
    int b = blockIdx.z, m0 = blockIdx.x * 128, n0 = blockIdx.y * 128;
    float acc[4][8][4];
    #pragma unroll
    for (int i = 0; i < 4; i++)
        #pragma unroll
        for (int j = 0; j < 8; j++)
            #pragma unroll
            for (int k = 0; k < 4; k++) acc[i][j][k] = 0.0f;

    gemm_core<1>(g_buf1 + (size_t)b * HW_ * C_, C_, g_owR, m0, n0, tid, sm, acc);

    epi_nchw(sm, acc, tid, out + (size_t)b * C_ * HW_, HW_, m0, n0, AddBias{ob});
}

// ===========================================================================
// Fused DCT -> gate -> iDCT per (b,c) image, tf32 mma (one image per block,
// 58 KB smem, 8 warps, warp tile 16x32). W and xs arrive pre-rounded ->
// tile loads are raw uint4 copies.
// ---------------------------------------------------------------------------
#define DS 76
#define DTILE (64 * DS)
#define DCT_SMEM_BYTES (3 * DTILE * 4)

__device__ __forceinline__ void dct_mm(const uint32_t* __restrict__ pA,
                                       const uint32_t* __restrict__ pB,
                                       float acc[4][4], int r, int nb,
                                       int g, int t4) {
    #pragma unroll
    for (int nf = 0; nf < 4; nf++)
        #pragma unroll
        for (int j = 0; j < 4; j++) acc[nf][j] = 0.0f;
    #pragma unroll
    for (int k8 = 0; k8 < 8; k8++) {
        uint32_t a0 = pA[r * DS + k8 * 8 + t4];
        uint32_t a1 = pA[(r + 8) * DS + k8 * 8 + t4];
        uint32_t a2 = pA[r * DS + k8 * 8 + t4 + 4];
        uint32_t a3 = pA[(r + 8) * DS + k8 * 8 + t4 + 4];
        #pragma unroll
        for (int nf = 0; nf < 4; nf++) {
            int n = nb + nf * 8 + g;
            uint32_t b0 = pB[(k8 * 8 + t4) * DS + n];
            uint32_t b1 = pB[(k8 * 8 + t4 + 4) * DS + n];
            mma8(acc[nf], a0, a1, a2, a3, b0, b1);
        }
    }
}

__global__ void __launch_bounds__(256) k_dct_mma() {
    extern __shared__ uint32_t dsm[];
    uint32_t* tW = dsm;
    uint32_t* tA = dsm + DTILE;
    uint32_t* tB = dsm + 2 * DTILE;
    int bc = blockIdx.x;
    int c = bc % C_;
    int tid = threadIdx.x;
    const uint4* xim4 = (const uint4*)(g_buf1 + (size_t)bc * HW_);
    const uint4* w4p = (const uint4*)g_W;
    #pragma unroll
    for (int i = tid; i < 1024; i += 256) {
        int h = i >> 4, w4 = (i & 15) * 4;
        *(uint4*)(tW + h * DS + w4) = w4p[i];
        *(uint4*)(tA + h * DS + w4) = xim4[i];
    }
    __syncthreads();

    int lane = tid & 31, g = lane >> 2, t4 = lane & 3;
    int warp = tid >> 5, wm = warp & 3, wn = warp >> 2;
    int r = wm * 16 + g, nb = wn * 32;
    float acc[4][4];

    // mm1: M1[n][w] = sum_h W[n][h] X[h][w]  -> store transposed tB[w][n]
    dct_mm(tW, tA, acc, r, nb, g, t4);
    #pragma unroll
    for (int nf = 0; nf < 4; nf++) {
        int cc = nb + nf * 8 + 2 * t4;
        tB[cc * DS + r]           = f2tf(acc[nf][0]);
        tB[(cc + 1) * DS + r]     = f2tf(acc[nf][1]);
        tB[cc * DS + r + 8]       = f2tf(acc[nf][2]);
        tB[(cc + 1) * DS + r + 8] = f2tf(acc[nf][3]);
    }
    __syncthreads();

    // mm2: XdT[k][n] = sum_w W[k][w] M1T[w][n]; gate; store tA[k][n]
    dct_mm(tW, tB, acc, r, nb, g, t4);
    {
        const float* gp = g_gate + (size_t)c * HW_;
        #pragma unroll
        for (int nf = 0; nf < 4; nf++) {
            int cc = nb + nf * 8 + 2 * t4;
            float g0 = gp[cc * 64 + r];
            float g1 = gp[(cc + 1) * 64 + r];
            float g2 = gp[cc * 64 + r + 8];
            float g3 = gp[(cc + 1) * 64 + r + 8];
            tA[r * DS + cc]           = f2tf(acc[nf][0] * g0);
            tA[r * DS + cc + 1]       = f2tf(acc[nf][1] * g1);
            tA[(r + 8) * DS + cc]     = f2tf(acc[nf][2] * g2);
            tA[(r + 8) * DS + cc + 1] = f2tf(acc[nf][3] * g3);
        }
    }
    __syncthreads();

    // mm3: M2T[k][h] = sum_n F[k][n] W[n][h] -> store transposed tB[h][k]
    dct_mm(tA, tW, acc, r, nb, g, t4);
    #pragma unroll
    for (int nf = 0; nf < 4; nf++) {
        int cc = nb + nf * 8 + 2 * t4;
        tB[cc * DS + r]           = f2tf(acc[nf][0]);
        tB[(cc + 1) * DS + r]     = f2tf(acc[nf][1]);
        tB[cc * DS + r + 8]       = f2tf(acc[nf][2]);
        tB[(cc + 1) * DS + r + 8] = f2tf(acc[nf][3]);
    }
    __syncthreads();

    // mm4: xi[h][w] = sum_k M2T[k][h] W[k][w] -> gmem
    dct_mm(tB, tW, acc, r, nb, g, t4);
    float* xo = g_buf0 + (size_t)bc * HW_;
    #pragma unroll
    for (int nf = 0; nf < 4; nf++) {
        int cc = nb + nf * 8 + 2 * t4;
        *(float2*)(xo + r * 64 + cc)       = make_float2(acc[nf][0], acc[nf][1]);
        *(float2*)(xo + (r + 8) * 64 + cc) = make_float2(acc[nf][2], acc[nf][3]);
    }
}

// ---------------------------------------------------------------------------
// LayerNorm over channels + SiLU(z) gate. 32 tokens per block of 256 threads
// (full 128B-line coalescing on the NCHW xi gather). Dynamic smem 52 KB.
// Output y tf32-pre-rounded (consumed only by out GEMM).
// ---------------------------------------------------------------------------
#define LNS 34
#define LN_SMEM_BYTES (C_ * LNS * 4)   // 52224

__global__ void __launch_bounds__(256) k_ln(const float* __restrict__ lng,
                                            const float* __restrict__ lnb) {
    extern __shared__ float s[];
    int tid = threadIdx.x;
    int mglob = blockIdx.x * 32;
    int b = mglob >> 12;
    int mloc = mglob & 4095;
    const float* xi = g_buf0 + (size_t)b * C_ * HW_ + mloc;
    #pragma unroll
    for (int i = tid; i < C_ * 32; i += 256) {
        int cc = i >> 5, t = i & 31;
        s[cc * LNS + t] = xi[(size_t)cc * HW_ + t];
    }
    __syncthreads();
    int tk = tid >> 3, g = tid & 7;
    float sum = 0.0f, ss = 0.0f;
    #pragma unroll 8
    for (int ii = 0; ii < 48; ii++) {
        int cc = g + ii * 8;
        float v = s[cc * LNS + tk];
        sum += v; ss += v * v;
    }
    #pragma unroll
    for (int off = 4; off; off >>= 1) {
        sum += __shfl_down_sync(0xffffffffu, sum, off);
        ss  += __shfl_down_sync(0xffffffffu, ss,  off);
    }
    int lane = tid & 31;
    int src = lane & ~7;
    sum = __shfl_sync(0xffffffffu, sum, src);
    ss  = __shfl_sync(0xffffffffu, ss,  src);
    float mu = sum * (1.0f / 384.0f);
    float var = ss * (1.0f / 384.0f) - mu * mu;
    float rstd = rsqrtf(fmaxf(var, 0.0f) + 1e-5f);

    int mt = mloc + tk;
    const float* zp = g_z + ((size_t)b * HW_ + mt) * C_;
    float* yp = g_buf1 + ((size_t)b * HW_ + mt) * C_;
    #pragma unroll 4
    for (int ii = 0; ii < 12; ii++) {
        int c0 = g * 48 + ii * 4;
        float4 zv = *(const float4*)(zp + c0);
        float4 gg = *(const float4*)(lng + c0);
        float4 bb = *(const float4*)(lnb + c0);
        float y0 = (s[(c0 + 0) * LNS + tk] - mu) * rstd * gg.x + bb.x;
        float y1 = (s[(c0 + 1) * LNS + tk] - mu) * rstd * gg.y + bb.y;
        float y2 = (s[(c0 + 2) * LNS + tk] - mu) * rstd * gg.z + bb.z;
        float y3 = (s[(c0 + 3) * LNS + tk] - mu) * rstd * gg.w + bb.w;
        y0 *= zv.x / (1.0f + __expf(-zv.x));
        y1 *= zv.y / (1.0f + __expf(-zv.y));
        y2 *= zv.z / (1.0f + __expf(-zv.z));
        y3 *= zv.w / (1.0f + __expf(-zv.w));
        *(float4*)(yp + c0) = make_float4(f2tf_f(y0), f2tf_f(y1),
                                          f2tf_f(y2), f2tf_f(y3));
    }
}

// ---------------------------------------------------------------------------
extern "C" void kernel_launch(void* const* d_in, const int* in_sizes, int n_in,
                              void* d_out, int out_size) {
    const float* x     = (const float*)d_in[0];
    const float* fe    = (const float*)d_in[1];
    const float* dw_w  = (const float*)d_in[2];
    const float* dw_b  = (const float*)d_in[3];
    const float* lin_w = (const float*)d_in[4];
    const float* lin_b = (const float*)d_in[5];
    const float* tok_w = (const float*)d_in[6];
    const float* tok_b = (const float*)d_in[7];
    const float* cc    = (const float*)d_in[8];
    const float* alpha = (const float*)d_in[9];
    const float* ln_g  = (const float*)d_in[10];
    const float* ln_b  = (const float*)d_in[11];
    const float* out_w = (const float*)d_in[12];
    const float* out_b = (const float*)d_in[13];
    float* out = (float*)d_out;

    cudaFuncSetAttribute(k_dct_mma, cudaFuncAttributeMaxDynamicSharedMemorySize,
                         DCT_SMEM_BYTES);
    cudaFuncSetAttribute(k_lin_mma, cudaFuncAttributeMaxDynamicSharedMemorySize,
                         GEMM_SMEM_BYTES);
    cudaFuncSetAttribute(k_gate_mma, cudaFuncAttributeMaxDynamicSharedMemorySize,
                         GEMM_SMEM_BYTES);
    cudaFuncSetAttribute(k_out_mma, cudaFuncAttributeMaxDynamicSharedMemorySize,
                         GEMM_SMEM_BYTES);
    cudaFuncSetAttribute(k_ln, cudaFuncAttributeMaxDynamicSharedMemorySize,
                         LN_SMEM_BYTES);

    // pre-round GEMM inputs to tf32 bit patterns
    k_round<<<(HW_ * C_ / 4 + 255) / 256, 256>>>(fe, 0, HW_ * C_ / 4);
    k_round<<<(2 * C_ * C_ / 4 + 255) / 256, 256>>>(lin_w, 1, 2 * C_ * C_ / 4);
    k_round<<<(C_ * C_ / 4 + 255) / 256, 256>>>(tok_w, 2, C_ * C_ / 4);
    k_round<<<(C_ * C_ / 4 + 255) / 256, 256>>>(out_w, 3, C_ * C_ / 4);

    k_dct_basis<<<64, 64>>>();
    k_dwconv<<<B_ * C_, 256>>>(x, dw_w, dw_b);
    k_gate_mma<<<dim3(32, 3), 128, GEMM_SMEM_BYTES>>>(tok_b, cc, alpha);
    k_lin_mma<<<dim3(32, 6, B_), 128, GEMM_SMEM_BYTES>>>(lin_b);
    k_dct_mma<<<B_ * C_, 256, DCT_SMEM_BYTES>>>();
    k_ln<<<(B_ * HW_) / 32, 256, LN_SMEM_BYTES>>>(ln_g, ln_b);
    k_out_mma<<<dim3(32, 3, B_), 128, GEMM_SMEM_BYTES>>>(out_b, out);
}

// round 15
// speedup vs baseline: 1.6573x; 1.0101x over previous
#include <cuda_runtime.h>
#include <math.h>
#include <stdint.h>

#define B_ 8
#define C_ 384
#define HW_ 4096

// Scratch (device globals — no runtime allocation)
__device__ float g_buf0[B_ * C_ * HW_];   // xdw (tf32-rounded), later xi
__device__ float g_buf1[B_ * C_ * HW_];   // xs (tf32-rounded), later y (tf32-rounded)
__device__ float g_z[B_ * HW_ * C_];      // z token-major (full f32)
__device__ float g_gate[C_ * HW_];        // spectral gate [c][n*64+k]
__device__ float g_W[64 * 64];            // DCT-II basis, tf32-rounded
// pre-rounded (tf32-bit) copies of GEMM inputs
__device__ float g_feR[HW_ * C_];
__device__ float g_lwR[2 * C_ * C_];
__device__ float g_twR[C_ * C_];
__device__ float g_owR[C_ * C_];

// ---------------------------------------------------------------------------
// helpers
// ---------------------------------------------------------------------------
__device__ __forceinline__ uint32_t f2tf(float f) {
    uint32_t u;
    asm("cvt.rna.tf32.f32 %0, %1;" : "=r"(u) : "f"(f));
    return u;
}
__device__ __forceinline__ float f2tf_f(float f) {
    return __uint_as_float(f2tf(f));
}

__device__ __forceinline__ void mma8(float* c, uint32_t a0, uint32_t a1,
                                     uint32_t a2, uint32_t a3,
                                     uint32_t b0, uint32_t b1) {
    asm volatile(
        "mma.sync.aligned.m16n8k8.row.col.f32.tf32.tf32.f32 "
        "{%0,%1,%2,%3}, {%4,%5,%6,%7}, {%8,%9}, {%0,%1,%2,%3};"
        : "+f"(c[0]), "+f"(c[1]), "+f"(c[2]), "+f"(c[3])
        : "r"(a0), "r"(a1), "r"(a2), "r"(a3), "r"(b0), "r"(b1));
}

__device__ __forceinline__ void cp16(uint32_t dst_smem, const void* src) {
    asm volatile("cp.async.cg.shared.global [%0], [%1], 16;"
                 :: "r"(dst_smem), "l"(src));
}

// ---------------------------------------------------------------------------
// Pre-round ALL GEMM inputs to tf32 bit patterns in ONE launch.
// float4 ranges: fe 393216 | lin_w 73728 | tok_w 36864 | out_w 36864
// ---------------------------------------------------------------------------
#define RND_FE  393216
#define RND_LW  (RND_FE + 73728)
#define RND_TW  (RND_LW + 36864)
#define RND_TOT (RND_TW + 36864)   // 540672

__global__ void k_round_all(const float* __restrict__ fe,
                            const float* __restrict__ lw,
                            const float* __restrict__ tw,
                            const float* __restrict__ ow) {
    int i = blockIdx.x * blockDim.x + threadIdx.x;
    if (i >= RND_TOT) return;
    const float4* src;
    float4* dst;
    int off;
    if (i < RND_FE)      { src = (const float4*)fe; dst = (float4*)g_feR; off = i; }
    else if (i < RND_LW) { src = (const float4*)lw; dst = (float4*)g_lwR; off = i - RND_FE; }
    else if (i < RND_TW) { src = (const float4*)tw; dst = (float4*)g_twR; off = i - RND_LW; }
    else                 { src = (const float4*)ow; dst = (float4*)g_owR; off = i - RND_TW; }
    float4 v = src[off];
    v.x = f2tf_f(v.x); v.y = f2tf_f(v.y);
    v.z = f2tf_f(v.z); v.w = f2tf_f(v.w);
    dst[off] = v;
}

// ---------------------------------------------------------------------------
// DCT basis (stored tf32-pre-rounded; consumed only as mma operand)
// ---------------------------------------------------------------------------
__global__ void k_dct_basis() {
    int n = blockIdx.x, x = threadIdx.x;
    float v = cosf((float)n * ((float)x + 0.5f) * (3.14159265358979323846f / 64.0f))
              * 0.17677669529663687f;
    if (n == 0) v *= 0.70710678118654752f;
    g_W[n * 64 + x] = f2tf_f(v);
}

// ---------------------------------------------------------------------------
// Depthwise 3x3 conv (SAME) + bias. One block per (b,c) image.
// smem [66][72]; interior loaded as float4; halo zeroed explicitly.
// Output tf32-pre-rounded, float4 stores.
// ---------------------------------------------------------------------------
__global__ void k_dwconv(const float* __restrict__ x,
                         const float* __restrict__ w,
                         const float* __restrict__ bias) {
    __shared__ float s[66 * 72];
    int bc = blockIdx.x;
    int tid = threadIdx.x;
    const float4* xim4 = (const float4*)(x + (size_t)bc * HW_);

    if (tid < 72) { s[tid] = 0.0f; s[65 * 72 + tid] = 0.0f; }
    if (tid < 64) { s[(tid + 1) * 72 + 3] = 0.0f; s[(tid + 1) * 72 + 68] = 0.0f; }

    #pragma unroll
    for (int i = tid; i < 1024; i += 256) {
        int h = i >> 4, w4 = (i & 15) * 4;
        *(float4*)(s + (h + 1) * 72 + 4 + w4) = xim4[i];
    }

    int c = bc % C_;
    const float* wp = w + c * 9;
    float w0 = wp[0], w1 = wp[1], w2 = wp[2];
    float w3 = wp[3], w4_ = wp[4], w5 = wp[5];
    float w6 = wp[6], w7 = wp[7], w8 = wp[8];
    float bv = bias[c];
    __syncthreads();

    float* outp = g_buf0 + (size_t)bc * HW_;
    #pragma unroll
    for (int i = tid; i < 1024; i += 256) {
        int h = i >> 4, ww = (i & 15) * 4;
        const float* r0 = s + h * 72 + ww + 3;
        const float* r1 = r0 + 72;
        const float* r2 = r0 + 144;
        float a0 = r0[0], a1 = r0[1], a2 = r0[2], a3 = r0[3], a4 = r0[4], a5 = r0[5];
        float b0 = r1[0], b1 = r1[1], b2 = r1[2], b3 = r1[3], b4 = r1[4], b5 = r1[5];
        float c0 = r2[0], c1 = r2[1], c2 = r2[2], c3 = r2[3], c4 = r2[4], c5 = r2[5];
        float o0 = bv, o1 = bv, o2 = bv, o3 = bv;
        o0 = fmaf(a0, w0, o0); o0 = fmaf(a1, w1, o0); o0 = fmaf(a2, w2, o0);
        o0 = fmaf(b0, w3, o0); o0 = fmaf(b1, w4_, o0); o0 = fmaf(b2, w5, o0);
        o0 = fmaf(c0, w6, o0); o0 = fmaf(c1, w7, o0); o0 = fmaf(c2, w8, o0);
        o1 = fmaf(a1, w0, o1); o1 = fmaf(a2, w1, o1); o1 = fmaf(a3, w2, o1);
        o1 = fmaf(b1, w3, o1); o1 = fmaf(b2, w4_, o1); o1 = fmaf(b3, w5, o1);
        o1 = fmaf(c1, w6, o1); o1 = fmaf(c2, w7, o1); o1 = fmaf(c3, w8, o1);
        o2 = fmaf(a2, w0, o2); o2 = fmaf(a3, w1, o2); o2 = fmaf(a4, w2, o2);
        o2 = fmaf(b2, w3, o2); o2 = fmaf(b3, w4_, o2); o2 = fmaf(b4, w5, o2);
        o2 = fmaf(c2, w6, o2); o2 = fmaf(c3, w7, o2); o2 = fmaf(c4, w8, o2);
        o3 = fmaf(a3, w0, o3); o3 = fmaf(a4, w1, o3); o3 = fmaf(a5, w2, o3);
        o3 = fmaf(b3, w3, o3); o3 = fmaf(b4, w4_, o3); o3 = fmaf(b5, w5, o3);
        o3 = fmaf(c3, w6, o3); o3 = fmaf(c4, w7, o3); o3 = fmaf(c5, w8, o3);
        *(float4*)(outp + i * 4) = make_float4(f2tf_f(o0), f2tf_f(o1),
                                               f2tf_f(o2), f2tf_f(o3));
    }
}

// ===========================================================================
// GEMM core v6: block 128(M) x 128(N), 128 threads = 4 warps (2m x 2n),
// warp tile 64x64. 3-stage cp.async ring, one sync per chunk.
// All GEMM inputs pre-rounded tf32 -> raw LDS -> mma.
// ---------------------------------------------------------------------------
#define STG_WORDS (2 * 128 * 36)                 // words per stage
#define GEMM_SMEM_BYTES (3 * STG_WORDS * 4)      // 110592

template<int AMODE>
__device__ __forceinline__ void stage_cp(uint32_t sbase, const float* __restrict__ Ag,
                                         int lda, const float* __restrict__ Bg,
                                         int m0, int n0, int kt, int tid) {
    if (AMODE == 0) {
        #pragma unroll
        for (int j = 0; j < 8; j++) {
            int id = tid + 128 * j;
            int kk = id >> 5, mc = (id & 31) * 4;
            cp16(sbase + (kk * 136 + mc) * 4,
                 Ag + (size_t)(kt + kk) * lda + m0 + mc);
        }
    } else {
        #pragma unroll
        for (int j = 0; j < 8; j++) {
            int k4 = tid & 7, mm = (tid >> 3) + 16 * j;
            cp16(sbase + (mm * 36 + 4 * k4) * 4,
                 Ag + (size_t)(m0 + mm) * lda + kt + 4 * k4);
        }
    }
    #pragma unroll
    for (int j = 0; j < 8; j++) {
        int k4 = tid & 7, nn = (tid >> 3) + 16 * j;
        cp16(sbase + (128 * 36 + nn * 36 + 4 * k4) * 4,
             Bg + (size_t)(n0 + nn) * C_ + kt + 4 * k4);
    }
    asm volatile("cp.async.commit_group;" ::: "memory");
}

template<int AMODE>
__device__ __forceinline__ void gemm_core(const float* __restrict__ Ag, int lda,
                                          const float* __restrict__ Bg,
                                          int m0, int n0, int tid,
                                          uint32_t* sm, float acc[4][8][4]) {
    int lane = tid & 31, g = lane >> 2, t4 = lane & 3;
    int warp = tid >> 5, wm = warp & 1, wn = warp >> 1;
    uint32_t sb = (uint32_t)__cvta_generic_to_shared(sm);

    stage_cp<AMODE>(sb,                 Ag, lda, Bg, m0, n0, 0,  tid);
    stage_cp<AMODE>(sb + STG_WORDS * 4, Ag, lda, Bg, m0, n0, 32, tid);

    #pragma unroll 1
    for (int kc = 0; kc < 12; kc++) {
        if (kc == 11) asm volatile("cp.async.wait_group 0;" ::: "memory");
        else          asm volatile("cp.async.wait_group 1;" ::: "memory");
        __syncthreads();
        if (kc + 2 < 12)
            stage_cp<AMODE>(sb + ((kc + 2) % 3) * STG_WORDS * 4,
                            Ag, lda, Bg, m0, n0, (kc + 2) * 32, tid);

        const uint32_t* sA = sm + (kc % 3) * STG_WORDS;
        const uint32_t* sB = sA + 128 * 36;
        #pragma unroll
        for (int k8 = 0; k8 < 4; k8++) {
            uint32_t a[4][4], bq[8][2];
            #pragma unroll
            for (int mf = 0; mf < 4; mf++) {
                int m = wm * 64 + mf * 16 + g;
                if (AMODE == 0) {
                    a[mf][0] = sA[(k8 * 8 + t4) * 136 + m];
                    a[mf][1] = sA[(k8 * 8 + t4) * 136 + m + 8];
                    a[mf][2] = sA[(k8 * 8 + t4 + 4) * 136 + m];
                    a[mf][3] = sA[(k8 * 8 + t4 + 4) * 136 + m + 8];
                } else {
                    const uint32_t* pa = sA + m * 36 + k8 * 8 + t4;
                    a[mf][0] = pa[0];
                    a[mf][1] = pa[8 * 36];
                    a[mf][2] = pa[4];
                    a[mf][3] = pa[8 * 36 + 4];
                }
            }
            #pragma unroll
            for (int nf = 0; nf < 8; nf++) {
                const uint32_t* pb = sB + (wn * 64 + nf * 8 + g) * 36 + k8 * 8 + t4;
                bq[nf][0] = pb[0];
                bq[nf][1] = pb[4];
            }
            #pragma unroll
            for (int mf = 0; mf < 4; mf++)
                #pragma unroll
                for (int nf = 0; nf < 8; nf++)
                    mma8(acc[mf][nf], a[mf][0], a[mf][1], a[mf][2], a[mf][3],
                         bq[nf][0], bq[nf][1]);
        }
        // no trailing sync: next chunk's top sync bounds skew
    }
}

// Chunked NCHW epilogue: 4 chunks of 32 channels, staged [ch][m] stride 132.
template<typename F>
__device__ __forceinline__ void epi_nchw(uint32_t* sm, float acc[4][8][4],
                                         int tid, float* dst, int strideM,
                                         int m0, int n0, F f) {
    float* sC = (float*)sm;
    int lane = tid & 31, g = lane >> 2, t4 = lane & 3;
    int warp = tid >> 5, wm = warp & 1, wn = warp >> 1;
    __syncthreads();
    #pragma unroll
    for (int c = 0; c < 4; c++) {
        if (wn == (c >> 1)) {
            int nf0 = 4 * (c & 1);
            #pragma unroll
            for (int mf = 0; mf < 4; mf++) {
                int r = wm * 64 + mf * 16 + g;
                #pragma unroll
                for (int nfl = 0; nfl < 4; nfl++) {
                    int nf = nf0 + nfl;
                    int chl = nfl * 8 + 2 * t4;
                    sC[chl * 132 + r]           = acc[mf][nf][0];
                    sC[(chl + 1) * 132 + r]     = acc[mf][nf][1];
                    sC[chl * 132 + r + 8]       = acc[mf][nf][2];
                    sC[(chl + 1) * 132 + r + 8] = acc[mf][nf][3];
                }
            }
        }
        __syncthreads();
        for (int i = tid; i < 4096; i += 128) {
            int ch = i >> 7, mm = i & 127;
            int gc = n0 + 32 * c + ch;
            dst[(size_t)gc * strideM + m0 + mm] = f(sC[ch * 132 + mm], gc);
        }
        __syncthreads();
    }
}

// ---------------------------------------------------------------------------
// lin GEMM: xz[m][d] = sum_c xdw[c][m]*lin_w[d][c] + lin_b[d]
// ---------------------------------------------------------------------------
struct AddBias {
    const float* b;
    __device__ float operator()(float v, int ch) const { return v + b[ch]; }
};
struct AddBiasRound {
    const float* b;
    __device__ float operator()(float v, int ch) const { return f2tf_f(v + b[ch]); }
};

__global__ void __launch_bounds__(128, 2) k_lin_mma(const float* __restrict__ lb) {
    extern __shared__ __align__(16) uint32_t sm[];
    int tid = threadIdx.x;
    int b = blockIdx.z, m0 = blockIdx.x * 128, n0 = blockIdx.y * 128;
    float acc[4][8][4];
    #pragma unroll
    for (int i = 0; i < 4; i++)
        #pragma unroll
        for (int j = 0; j < 8; j++)
            #pragma unroll
            for (int k = 0; k < 4; k++) acc[i][j][k] = 0.0f;

    gemm_core<0>(g_buf0 + (size_t)b * C_ * HW_, HW_, g_lwR, m0, n0, tid, sm, acc);

    if (n0 < C_) {
        epi_nchw(sm, acc, tid, g_buf1 + (size_t)b * C_ * HW_, HW_, m0, n0,
                 AddBiasRound{lb});
    } else {
        float* sC = (float*)sm;
        int lane = tid & 31, g = lane >> 2, t4 = lane & 3;
        int warp = tid >> 5, wm = warp & 1, wn = warp >> 1;
        float* zb = g_z + (size_t)b * HW_ * C_;
        int zoff = n0 - C_;
        __syncthreads();
        #pragma unroll
        for (int j = 0; j < 2; j++) {
            if (wm == j) {
                #pragma unroll
                for (int mf = 0; mf < 4; mf++) {
                    int rl = mf * 16 + g;
                    #pragma unroll
                    for (int nf = 0; nf < 8; nf++) {
                        int cc = wn * 64 + nf * 8 + 2 * t4;
                        *(float2*)(sC + rl * 132 + cc) =
                            make_float2(acc[mf][nf][0], acc[mf][nf][1]);
                        *(float2*)(sC + (rl + 8) * 132 + cc) =
                            make_float2(acc[mf][nf][2], acc[mf][nf][3]);
                    }
                }
            }
            __syncthreads();
            for (int i = tid; i < 2048; i += 128) {
                int row = i >> 5, q = i & 31;
                float4 v = *(float4*)(sC + row * 132 + 4 * q);
                float4 bb = *(const float4*)(lb + C_ + zoff + 4 * q);
                v.x += bb.x; v.y += bb.y; v.z += bb.z; v.w += bb.w;
                *(float4*)(zb + (size_t)(m0 + 64 * j + row) * C_ + zoff + 4 * q) = v;
            }
            __syncthreads();
        }
    }
}

// ---------------------------------------------------------------------------
// gate GEMM: t = relu(fe @ tok_w^T + tok_b); gate = cos(c*t)+sin(c*t)*(1+.5a)/c
// ---------------------------------------------------------------------------
struct GateXform {
    const float* tb;
    float c0, s1;
    __device__ float operator()(float v, int ch) const {
        float t = fmaxf(v + tb[ch], 0.0f);
        float ct = c0 * t;
        return cosf(ct) + sinf(ct) * s1;
    }
};

__global__ void __launch_bounds__(128, 2) k_gate_mma(const float* __restrict__ tb,
                                                     const float* __restrict__ cp,
                                                     const float* __restrict__ ap) {
    extern __shared__ __align__(16) uint32_t sm[];
    int tid = threadIdx.x;
    int m0 = blockIdx.x * 128, n0 = blockIdx.y * 128;
    float acc[4][8][4];
    #pragma unroll
    for (int i = 0; i < 4; i++)
        #pragma unroll
        for (int j = 0; j < 8; j++)
            #pragma unroll
            for (int k = 0; k < 4; k++) acc[i][j][k] = 0.0f;

    gemm_core<1>(g_feR, C_, g_twR, m0, n0, tid, sm, acc);

    float c0 = cp[0];
    float s1 = (1.0f + 0.5f * ap[0]) / c0;
    epi_nchw(sm, acc, tid, g_gate, HW_, m0, n0, GateXform{tb, c0, s1});
}

// ---------------------------------------------------------------------------
// out GEMM: out[d][m] = sum_c y[m][c]*out_w[d][c] + out_b[d]
// ---------------------------------------------------------------------------
__global__ void __launch_bounds__(128, 2) k_out_mma(const float* __restrict__ ob,
                                                    float* __restrict__ out) {
    extern __shared__ __align__(16) uint32_t sm[];
    int tid = threadIdx.x;
    int b = blockIdx.z, m0 = blockIdx.x * 128, n0 = blockIdx.y * 128;
    float acc[4][8][4];
    #pragma unroll
    for (int i = 0; i < 4; i++)
        #pragma unroll
        for (int j = 0; j < 8; j++)
            #pragma unroll
            for (int k = 0; k < 4; k++) acc[i][j][k] = 0.0f;

    gemm_core<1>(g_buf1 + (size_t)b * HW_ * C_, C_, g_owR, m0, n0, tid, sm, acc);

    epi_nchw(sm, acc, tid, out + (size_t)b * C_ * HW_, HW_, m0, n0, AddBias{ob});
}

// ===========================================================================
// Fused DCT -> gate -> iDCT per (b,c) image, tf32 mma (one image per block,
// 58 KB smem, 8 warps, warp tile 16x32). Gate prefetched into registers
// BEFORE tile staging (overlaps gmem latency with smem fills + mm1/mm2).
// __launch_bounds__(256, 3): 3 blocks/SM (24 warps) for latency hiding.
// ---------------------------------------------------------------------------
#define DS 76
#define DTILE (64 * DS)
#define DCT_SMEM_BYTES (3 * DTILE * 4)

__device__ __forceinline__ void dct_mm(const uint32_t* __restrict__ pA,
                                       const uint32_t* __restrict__ pB,
                                       float acc[4][4], int r, int nb,
                                       int g, int t4) {
    #pragma unroll
    for (int nf = 0; nf < 4; nf++)
        #pragma unroll
        for (int j = 0; j < 4; j++) acc[nf][j] = 0.0f;
    #pragma unroll
    for (int k8 = 0; k8 < 8; k8++) {
        uint32_t a0 = pA[r * DS + k8 * 8 + t4];
        uint32_t a1 = pA[(r + 8) * DS + k8 * 8 + t4];
        uint32_t a2 = pA[r * DS + k8 * 8 + t4 + 4];
        uint32_t a3 = pA[(r + 8) * DS + k8 * 8 + t4 + 4];
        #pragma unroll
        for (int nf = 0; nf < 4; nf++) {
            int n = nb + nf * 8 + g;
            uint32_t b0 = pB[(k8 * 8 + t4) * DS + n];
            uint32_t b1 = pB[(k8 * 8 + t4 + 4) * DS + n];
            mma8(acc[nf], a0, a1, a2, a3, b0, b1);
        }
    }
}

__global__ void __launch_bounds__(256, 3) k_dct_mma() {
    extern __shared__ uint32_t dsm[];
    uint32_t* tW = dsm;
    uint32_t* tA = dsm + DTILE;
    uint32_t* tB = dsm + 2 * DTILE;
    int bc = blockIdx.x;
    int c = bc % C_;
    int tid = threadIdx.x;
    int lane = tid & 31, g = lane >> 2, t4 = lane & 3;
    int warp = tid >> 5, wm = warp & 3, wn = warp >> 2;
    int r = wm * 16 + g, nb = wn * 32;

    // Prefetch gate values (used after mm2) BEFORE tile staging: LDG latency
    // overlaps the smem fills and the first two matmul phases.
    float gv[4][4];
    {
        const float* gp = g_gate + (size_t)c * HW_;
        #pragma unroll
        for (int nf = 0; nf < 4; nf++) {
            int cc = nb + nf * 8 + 2 * t4;
            gv[nf][0] = gp[cc * 64 + r];
            gv[nf][1] = gp[(cc + 1) * 64 + r];
            gv[nf][2] = gp[cc * 64 + r + 8];
            gv[nf][3] = gp[(cc + 1) * 64 + r + 8];
        }
    }

    const uint4* xim4 = (const uint4*)(g_buf1 + (size_t)bc * HW_);
    const uint4* w4p = (const uint4*)g_W;
    #pragma unroll
    for (int i = tid; i < 1024; i += 256) {
        int h = i >> 4, w4 = (i & 15) * 4;
        *(uint4*)(tW + h * DS + w4) = w4p[i];
        *(uint4*)(tA + h * DS + w4) = xim4[i];
    }
    __syncthreads();

    float acc[4][4];

    // mm1: M1[n][w] = sum_h W[n][h] X[h][w]  -> store transposed tB[w][n]
    dct_mm(tW, tA, acc, r, nb, g, t4);
    #pragma unroll
    for (int nf = 0; nf < 4; nf++) {
        int cc = nb + nf * 8 + 2 * t4;
        tB[cc * DS + r]           = f2tf(acc[nf][0]);
        tB[(cc + 1) * DS + r]     = f2tf(acc[nf][1]);
        tB[cc * DS + r + 8]       = f2tf(acc[nf][2]);
        tB[(cc + 1) * DS + r + 8] = f2tf(acc[nf][3]);
    }
    __syncthreads();

    // mm2: XdT[k][n] = sum_w W[k][w] M1T[w][n]; gate; store tA[k][n]
    dct_mm(tW, tB, acc, r, nb, g, t4);
    #pragma unroll
    for (int nf = 0; nf < 4; nf++) {
        int cc = nb + nf * 8 + 2 * t4;
        tA[r * DS + cc]           = f2tf(acc[nf][0] * gv[nf][0]);
        tA[r * DS + cc + 1]       = f2tf(acc[nf][1] * gv[nf][1]);
        tA[(r + 8) * DS + cc]     = f2tf(acc[nf][2] * gv[nf][2]);
        tA[(r + 8) * DS + cc + 1] = f2tf(acc[nf][3] * gv[nf][3]);
    }
    __syncthreads();

    // mm3: M2T[k][h] = sum_n F[k][n] W[n][h] -> store transposed tB[h][k]
    dct_mm(tA, tW, acc, r, nb, g, t4);
    #pragma unroll
    for (int nf = 0; nf < 4; nf++) {
        int cc = nb + nf * 8 + 2 * t4;
        tB[cc * DS + r]           = f2tf(acc[nf][0]);
        tB[(cc + 1) * DS + r]     = f2tf(acc[nf][1]);
        tB[cc * DS + r + 8]       = f2tf(acc[nf][2]);
        tB[(cc + 1) * DS + r + 8] = f2tf(acc[nf][3]);
    }
    __syncthreads();

    // mm4: xi[h][w] = sum_k M2T[k][h] W[k][w] -> gmem
    dct_mm(tB, tW, acc, r, nb, g, t4);
    float* xo = g_buf0 + (size_t)bc * HW_;
    #pragma unroll
    for (int nf = 0; nf < 4; nf++) {
        int cc = nb + nf * 8 + 2 * t4;
        *(float2*)(xo + r * 64 + cc)       = make_float2(acc[nf][0], acc[nf][1]);
        *(float2*)(xo + (r + 8) * 64 + cc) = make_float2(acc[nf][2], acc[nf][3]);
    }
}

// ---------------------------------------------------------------------------
// LayerNorm over channels + SiLU(z) gate. 32 tokens per block of 256 threads.
// Output y tf32-pre-rounded (consumed only by out GEMM).
// ---------------------------------------------------------------------------
#define LNS 34
#define LN_SMEM_BYTES (C_ * LNS * 4)   // 52224

__global__ void __launch_bounds__(256) k_ln(const float* __restrict__ lng,
                                            const float* __restrict__ lnb) {
    extern __shared__ float s[];
    int tid = threadIdx.x;
    int mglob = blockIdx.x * 32;
    int b = mglob >> 12;
    int mloc = mglob & 4095;
    const float* xi = g_buf0 + (size_t)b * C_ * HW_ + mloc;
    #pragma unroll
    for (int i = tid; i < C_ * 32; i += 256) {
        int cc = i >> 5, t = i & 31;
        s[cc * LNS + t] = xi[(size_t)cc * HW_ + t];
    }
    __syncthreads();
    int tk = tid >> 3, g = tid & 7;
    float sum = 0.0f, ss = 0.0f;
    #pragma unroll 8
    for (int ii = 0; ii < 48; ii++) {
        int cc = g + ii * 8;
        float v = s[cc * LNS + tk];
        sum += v; ss += v * v;
    }
    #pragma unroll
    for (int off = 4; off; off >>= 1) {
        sum += __shfl_down_sync(0xffffffffu, sum, off);
        ss  += __shfl_down_sync(0xffffffffu, ss,  off);
    }
    int lane = tid & 31;
    int src = lane & ~7;
    sum = __shfl_sync(0xffffffffu, sum, src);
    ss  = __shfl_sync(0xffffffffu, ss,  src);
    float mu = sum * (1.0f / 384.0f);
    float var = ss * (1.0f / 384.0f) - mu * mu;
    float rstd = rsqrtf(fmaxf(var, 0.0f) + 1e-5f);

    int mt = mloc + tk;
    const float* zp = g_z + ((size_t)b * HW_ + mt) * C_;
    float* yp = g_buf1 + ((size_t)b * HW_ + mt) * C_;
    #pragma unroll 4
    for (int ii = 0; ii < 12; ii++) {
        int c0 = g * 48 + ii * 4;
        float4 zv = *(const float4*)(zp + c0);
        float4 gg = *(const float4*)(lng + c0);
        float4 bb = *(const float4*)(lnb + c0);
        float y0 = (s[(c0 + 0) * LNS + tk] - mu) * rstd * gg.x + bb.x;
        float y1 = (s[(c0 + 1) * LNS + tk] - mu) * rstd * gg.y + bb.y;
        float y2 = (s[(c0 + 2) * LNS + tk] - mu) * rstd * gg.z + bb.z;
        float y3 = (s[(c0 + 3) * LNS + tk] - mu) * rstd * gg.w + bb.w;
        y0 *= zv.x / (1.0f + __expf(-zv.x));
        y1 *= zv.y / (1.0f + __expf(-zv.y));
        y2 *= zv.z / (1.0f + __expf(-zv.z));
        y3 *= zv.w / (1.0f + __expf(-zv.w));
        *(float4*)(yp + c0) = make_float4(f2tf_f(y0), f2tf_f(y1),
                                          f2tf_f(y2), f2tf_f(y3));
    }
}

// ---------------------------------------------------------------------------
extern "C" void kernel_launch(void* const* d_in, const int* in_sizes, int n_in,
                              void* d_out, int out_size) {
    const float* x     = (const float*)d_in[0];
    const float* fe    = (const float*)d_in[1];
    const float* dw_w  = (const float*)d_in[2];
    const float* dw_b  = (const float*)d_in[3];
    const float* lin_w = (const float*)d_in[4];
    const float* lin_b = (const float*)d_in[5];
    const float* tok_w = (const float*)d_in[6];
    const float* tok_b = (const float*)d_in[7];
    const float* cc    = (const float*)d_in[8];
    const float* alpha = (const float*)d_in[9];
    const float* ln_g  = (const float*)d_in[10];
    const float* ln_b  = (const float*)d_in[11];
    const float* out_w = (const float*)d_in[12];
    const float* out_b = (const float*)d_in[13];
    float* out = (float*)d_out;

    cudaFuncSetAttribute(k_dct_mma, cudaFuncAttributeMaxDynamicSharedMemorySize,
                         DCT_SMEM_BYTES);
    cudaFuncSetAttribute(k_lin_mma, cudaFuncAttributeMaxDynamicSharedMemorySize,
                         GEMM_SMEM_BYTES);
    cudaFuncSetAttribute(k_gate_mma, cudaFuncAttributeMaxDynamicSharedMemorySize,
                         GEMM_SMEM_BYTES);
    cudaFuncSetAttribute(k_out_mma, cudaFuncAttributeMaxDynamicSharedMemorySize,
                         GEMM_SMEM_BYTES);
    cudaFuncSetAttribute(k_ln, cudaFuncAttributeMaxDynamicSharedMemorySize,
                         LN_SMEM_BYTES);

    // pre-round all GEMM inputs in one launch
    k_round_all<<<(RND_TOT + 255) / 256, 256>>>(fe, lin_w, tok_w, out_w);

    k_dct_basis<<<64, 64>>>();
    k_dwconv<<<B_ * C_, 256>>>(x, dw_w, dw_b);
    k_gate_mma<<<dim3(32, 3), 128, GEMM_SMEM_BYTES>>>(tok_b, cc, alpha);
    k_lin_mma<<<dim3(32, 6, B_), 128, GEMM_SMEM_BYTES>>>(lin_b);
    k_dct_mma<<<B_ * C_, 256, DCT_SMEM_BYTES>>>();
    k_ln<<<(B_ * HW_) / 32, 256, LN_SMEM_BYTES>>>(ln_g, ln_b);
    k_out_mma<<<dim3(32, 3, B_), 128, GEMM_SMEM_BYTES>>>(out_b, out);
}

// round 17
// speedup vs baseline: 1.7414x; 1.0507x over previous
#include <cuda_runtime.h>
#include <math.h>
#include <stdint.h>

#define B_ 8
#define C_ 384
#define HW_ 4096

// Scratch (device globals — no runtime allocation)
__device__ float g_buf0[B_ * C_ * HW_];   // xdw (tf32-rounded), later xi
__device__ float g_buf1[B_ * C_ * HW_];   // xs (tf32-rounded), later y (tf32-rounded)
__device__ float g_z[B_ * HW_ * C_];      // z token-major (full f32)
__device__ float g_gate[C_ * HW_];        // spectral gate [c][n*64+k]
__device__ float g_W[64 * 64];            // DCT-II basis, tf32-rounded
// pre-rounded (tf32-bit) copies of GEMM inputs
__device__ float g_feR[HW_ * C_];
__device__ float g_lwR[2 * C_ * C_];
__device__ float g_twR[C_ * C_];
__device__ float g_owR[C_ * C_];

// ---------------------------------------------------------------------------
// helpers
// ---------------------------------------------------------------------------
__device__ __forceinline__ uint32_t f2tf(float f) {
    uint32_t u;
    asm("cvt.rna.tf32.f32 %0, %1;" : "=r"(u) : "f"(f));
    return u;
}
__device__ __forceinline__ float f2tf_f(float f) {
    return __uint_as_float(f2tf(f));
}

__device__ __forceinline__ void mma8(float* c, uint32_t a0, uint32_t a1,
                                     uint32_t a2, uint32_t a3,
                                     uint32_t b0, uint32_t b1) {
    asm volatile(
        "mma.sync.aligned.m16n8k8.row.col.f32.tf32.tf32.f32 "
        "{%0,%1,%2,%3}, {%4,%5,%6,%7}, {%8,%9}, {%0,%1,%2,%3};"
        : "+f"(c[0]), "+f"(c[1]), "+f"(c[2]), "+f"(c[3])
        : "r"(a0), "r"(a1), "r"(a2), "r"(a3), "r"(b0), "r"(b1));
}

__device__ __forceinline__ void cp16(uint32_t dst_smem, const void* src) {
    asm volatile("cp.async.cg.shared.global [%0], [%1], 16;"
                 :: "r"(dst_smem), "l"(src));
}

// ---------------------------------------------------------------------------
// k_prep: ONE launch fusing three independent prep tasks by block range:
//   [0, 3072)        depthwise 3x3 conv (one block per (b,c) image)
//   [3072, 5184)     tf32 pre-round of fe / lin_w / tok_w / out_w (float4 each)
//   [5184]           DCT basis
// ---------------------------------------------------------------------------
#define RND_FE  393216
#define RND_LW  (RND_FE + 73728)
#define RND_TW  (RND_LW + 36864)
#define RND_TOT (RND_TW + 36864)   // 540672 float4s = 2112 blocks x 256

#define PREP_DW   3072
#define PREP_RND  (PREP_DW + 2112)   // 5184
#define PREP_GRID (PREP_RND + 1)     // 5185

__global__ void __launch_bounds__(256) k_prep(
        const float* __restrict__ x, const float* __restrict__ dw_w,
        const float* __restrict__ dw_b,
        const float* __restrict__ fe, const float* __restrict__ lw,
        const float* __restrict__ tw, const float* __restrict__ ow) {
    __shared__ float s[66 * 72];
    int bid = blockIdx.x;
    int tid = threadIdx.x;

    if (bid < PREP_DW) {
        // ---- depthwise conv ----
        int bc = bid;
        const float4* xim4 = (const float4*)(x + (size_t)bc * HW_);
        if (tid < 72) { s[tid] = 0.0f; s[65 * 72 + tid] = 0.0f; }
        if (tid < 64) { s[(tid + 1) * 72 + 3] = 0.0f; s[(tid + 1) * 72 + 68] = 0.0f; }
        #pragma unroll
        for (int i = tid; i < 1024; i += 256) {
            int h = i >> 4, w4 = (i & 15) * 4;
            *(float4*)(s + (h + 1) * 72 + 4 + w4) = xim4[i];
        }
        int c = bc % C_;
        const float* wp = dw_w + c * 9;
        float w0 = wp[0], w1 = wp[1], w2 = wp[2];
        float w3 = wp[3], w4_ = wp[4], w5 = wp[5];
        float w6 = wp[6], w7 = wp[7], w8 = wp[8];
        float bv = dw_b[c];
        __syncthreads();
        float* outp = g_buf0 + (size_t)bc * HW_;
        #pragma unroll
        for (int i = tid; i < 1024; i += 256) {
            int h = i >> 4, ww = (i & 15) * 4;
            const float* r0 = s + h * 72 + ww + 3;
            const float* r1 = r0 + 72;
            const float* r2 = r0 + 144;
            float a0 = r0[0], a1 = r0[1], a2 = r0[2], a3 = r0[3], a4 = r0[4], a5 = r0[5];
            float b0 = r1[0], b1 = r1[1], b2 = r1[2], b3 = r1[3], b4 = r1[4], b5 = r1[5];
            float c0 = r2[0], c1 = r2[1], c2 = r2[2], c3 = r2[3], c4 = r2[4], c5 = r2[5];
            float o0 = bv, o1 = bv, o2 = bv, o3 = bv;
            o0 = fmaf(a0, w0, o0); o0 = fmaf(a1, w1, o0); o0 = fmaf(a2, w2, o0);
            o0 = fmaf(b0, w3, o0); o0 = fmaf(b1, w4_, o0); o0 = fmaf(b2, w5, o0);
            o0 = fmaf(c0, w6, o0); o0 = fmaf(c1, w7, o0); o0 = fmaf(c2, w8, o0);
            o1 = fmaf(a1, w0, o1); o1 = fmaf(a2, w1, o1); o1 = fmaf(a3, w2, o1);
            o1 = fmaf(b1, w3, o1); o1 = fmaf(b2, w4_, o1); o1 = fmaf(b3, w5, o1);
            o1 = fmaf(c1, w6, o1); o1 = fmaf(c2, w7, o1); o1 = fmaf(c3, w8, o1);
            o2 = fmaf(a2, w0, o2); o2 = fmaf(a3, w1, o2); o2 = fmaf(a4, w2, o2);
            o2 = fmaf(b2, w3, o2); o2 = fmaf(b3, w4_, o2); o2 = fmaf(b4, w5, o2);
            o2 = fmaf(c2, w6, o2); o2 = fmaf(c3, w7, o2); o2 = fmaf(c4, w8, o2);
            o3 = fmaf(a3, w0, o3); o3 = fmaf(a4, w1, o3); o3 = fmaf(a5, w2, o3);
            o3 = fmaf(b3, w3, o3); o3 = fmaf(b4, w4_, o3); o3 = fmaf(b5, w5, o3);
            o3 = fmaf(c3, w6, o3); o3 = fmaf(c4, w7, o3); o3 = fmaf(c5, w8, o3);
            *(float4*)(outp + i * 4) = make_float4(f2tf_f(o0), f2tf_f(o1),
                                                   f2tf_f(o2), f2tf_f(o3));
        }
    } else if (bid < PREP_RND) {
        // ---- tf32 pre-round ----
        int i = (bid - PREP_DW) * 256 + tid;
        if (i < RND_TOT) {
            const float4* src;
            float4* dst;
            int off;
            if (i < RND_FE)      { src = (const float4*)fe; dst = (float4*)g_feR; off = i; }
            else if (i < RND_LW) { src = (const float4*)lw; dst = (float4*)g_lwR; off = i - RND_FE; }
            else if (i < RND_TW) { src = (const float4*)tw; dst = (float4*)g_twR; off = i - RND_LW; }
            else                 { src = (const float4*)ow; dst = (float4*)g_owR; off = i - RND_TW; }
            float4 v = src[off];
            v.x = f2tf_f(v.x); v.y = f2tf_f(v.y);
            v.z = f2tf_f(v.z); v.w = f2tf_f(v.w);
            dst[off] = v;
        }
    } else {
        // ---- DCT basis ----
        for (int i = tid; i < 4096; i += 256) {
            int n = i >> 6, xx = i & 63;
            float v = cosf((float)n * ((float)xx + 0.5f) *
                           (3.14159265358979323846f / 64.0f)) * 0.17677669529663687f;
            if (n == 0) v *= 0.70710678118654752f;
            g_W[i] = f2tf_f(v);
        }
    }
}

// ===========================================================================
// GEMM core v6: block 128(M) x 128(N), 128 threads = 4 warps (2m x 2n),
// warp tile 64x64. 3-stage cp.async ring, one sync per chunk.
// All GEMM inputs pre-rounded tf32 -> raw LDS -> mma.
// ---------------------------------------------------------------------------
#define STG_WORDS (2 * 128 * 36)                 // words per stage
#define GEMM_SMEM_BYTES (3 * STG_WORDS * 4)      // 110592

template<int AMODE>
__device__ __forceinline__ void stage_cp(uint32_t sbase, const float* __restrict__ Ag,
                                         int lda, const float* __restrict__ Bg,
                                         int m0, int n0, int kt, int tid) {
    if (AMODE == 0) {
        #pragma unroll
        for (int j = 0; j < 8; j++) {
            int id = tid + 128 * j;
            int kk = id >> 5, mc = (id & 31) * 4;
            cp16(sbase + (kk * 136 + mc) * 4,
                 Ag + (size_t)(kt + kk) * lda + m0 + mc);
        }
    } else {
        #pragma unroll
        for (int j = 0; j < 8; j++) {
            int k4 = tid & 7, mm = (tid >> 3) + 16 * j;
            cp16(sbase + (mm * 36 + 4 * k4) * 4,
                 Ag + (size_t)(m0 + mm) * lda + kt + 4 * k4);
        }
    }
    #pragma unroll
    for (int j = 0; j < 8; j++) {
        int k4 = tid & 7, nn = (tid >> 3) + 16 * j;
        cp16(sbase + (128 * 36 + nn * 36 + 4 * k4) * 4,
             Bg + (size_t)(n0 + nn) * C_ + kt + 4 * k4);
    }
    asm volatile("cp.async.commit_group;" ::: "memory");
}

template<int AMODE>
__device__ __forceinline__ void gemm_core(const float* __restrict__ Ag, int lda,
                                          const float* __restrict__ Bg,
                                          int m0, int n0, int tid,
                                          uint32_t* sm, float acc[4][8][4]) {
    int lane = tid & 31, g = lane >> 2, t4 = lane & 3;
    int warp = tid >> 5, wm = warp & 1, wn = warp >> 1;
    uint32_t sb = (uint32_t)__cvta_generic_to_shared(sm);

    stage_cp<AMODE>(sb,                 Ag, lda, Bg, m0, n0, 0,  tid);
    stage_cp<AMODE>(sb + STG_WORDS * 4, Ag, lda, Bg, m0, n0, 32, tid);

    #pragma unroll 1
    for (int kc = 0; kc < 12; kc++) {
        if (kc == 11) asm volatile("cp.async.wait_group 0;" ::: "memory");
        else          asm volatile("cp.async.wait_group 1;" ::: "memory");
        __syncthreads();
        if (kc + 2 < 12)
            stage_cp<AMODE>(sb + ((kc + 2) % 3) * STG_WORDS * 4,
                            Ag, lda, Bg, m0, n0, (kc + 2) * 32, tid);

        const uint32_t* sA = sm + (kc % 3) * STG_WORDS;
        const uint32_t* sB = sA + 128 * 36;
        #pragma unroll
        for (int k8 = 0; k8 < 4; k8++) {
            uint32_t a[4][4], bq[8][2];
            #pragma unroll
            for (int mf = 0; mf < 4; mf++) {
                int m = wm * 64 + mf * 16 + g;
                if (AMODE == 0) {
                    a[mf][0] = sA[(k8 * 8 + t4) * 136 + m];
                    a[mf][1] = sA[(k8 * 8 + t4) * 136 + m + 8];
                    a[mf][2] = sA[(k8 * 8 + t4 + 4) * 136 + m];
                    a[mf][3] = sA[(k8 * 8 + t4 + 4) * 136 + m + 8];
                } else {
                    const uint32_t* pa = sA + m * 36 + k8 * 8 + t4;
                    a[mf][0] = pa[0];
                    a[mf][1] = pa[8 * 36];
                    a[mf][2] = pa[4];
                    a[mf][3] = pa[8 * 36 + 4];
                }
            }
            #pragma unroll
            for (int nf = 0; nf < 8; nf++) {
                const uint32_t* pb = sB + (wn * 64 + nf * 8 + g) * 36 + k8 * 8 + t4;
                bq[nf][0] = pb[0];
                bq[nf][1] = pb[4];
            }
            #pragma unroll
            for (int mf = 0; mf < 4; mf++)
                #pragma unroll
                for (int nf = 0; nf < 8; nf++)
                    mma8(acc[mf][nf], a[mf][0], a[mf][1], a[mf][2], a[mf][3],
                         bq[nf][0], bq[nf][1]);
        }
        // no trailing sync: next chunk's top sync bounds skew
    }
}

// Chunked NCHW epilogue: 4 chunks of 32 channels, staged [ch][m] stride 132.
template<typename F>
__device__ __forceinline__ void epi_nchw(uint32_t* sm, float acc[4][8][4],
                                         int tid, float* dst, int strideM,
                                         int m0, int n0, F f) {
    float* sC = (float*)sm;
    int lane = tid & 31, g = lane >> 2, t4 = lane & 3;
    int warp = tid >> 5, wm = warp & 1, wn = warp >> 1;
    __syncthreads();
    #pragma unroll
    for (int c = 0; c < 4; c++) {
        if (wn == (c >> 1)) {
            int nf0 = 4 * (c & 1);
            #pragma unroll
            for (int mf = 0; mf < 4; mf++) {
                int r = wm * 64 + mf * 16 + g;
                #pragma unroll
                for (int nfl = 0; nfl < 4; nfl++) {
                    int nf = nf0 + nfl;
                    int chl = nfl * 8 + 2 * t4;
                    sC[chl * 132 + r]           = acc[mf][nf][0];
                    sC[(chl + 1) * 132 + r]     = acc[mf][nf][1];
                    sC[chl * 132 + r + 8]       = acc[mf][nf][2];
                    sC[(chl + 1) * 132 + r + 8] = acc[mf][nf][3];
                }
            }
        }
        __syncthreads();
        for (int i = tid; i < 4096; i += 128) {
            int ch = i >> 7, mm = i & 127;
            int gc = n0 + 32 * c + ch;
            dst[(size_t)gc * strideM + m0 + mm] = f(sC[ch * 132 + mm], gc);
        }
        __syncthreads();
    }
}

// ---------------------------------------------------------------------------
// Fused lin + gate GEMM launch. blockIdx.z < 8 -> lin (batch z); z == 8 ->
// gate (only y < 3 active). Gate blocks ride inside the big lin wave.
// lin: xz[m][d] = sum_c xdw[c][m]*lin_w[d][c] + lin_b[d]
// gate: t = relu(fe @ tok_w^T + tok_b); gate = cos(c*t)+sin(c*t)*(1+.5a)/c
// ---------------------------------------------------------------------------
struct AddBias {
    const float* b;
    __device__ float operator()(float v, int ch) const { return v + b[ch]; }
};
struct AddBiasRound {
    const float* b;
    __device__ float operator()(float v, int ch) const { return f2tf_f(v + b[ch]); }
};
struct GateXform {
    const float* tb;
    float c0, s1;
    __device__ float operator()(float v, int ch) const {
        float t = fmaxf(v + tb[ch], 0.0f);
        float ct = c0 * t;
        return cosf(ct) + sinf(ct) * s1;
    }
};

__global__ void __launch_bounds__(128, 2) k_lingate_mma(const float* __restrict__ lb,
                                                        const float* __restrict__ tb,
                                                        const float* __restrict__ cp,
                                                        const float* __restrict__ ap) {
    extern __shared__ __align__(16) uint32_t sm[];
    int tid = threadIdx.x;
    int z = blockIdx.z;
    int m0 = blockIdx.x * 128, n0 = blockIdx.y * 128;

    float acc[4][8][4];
    #pragma unroll
    for (int i = 0; i < 4; i++)
        #pragma unroll
        for (int j = 0; j < 8; j++)
            #pragma unroll
            for (int k = 0; k < 4; k++) acc[i][j][k] = 0.0f;

    if (z < 8) {
        // ---- lin GEMM, batch z ----
        gemm_core<0>(g_buf0 + (size_t)z * C_ * HW_, HW_, g_lwR, m0, n0, tid, sm, acc);

        if (n0 < C_) {
            epi_nchw(sm, acc, tid, g_buf1 + (size_t)z * C_ * HW_, HW_, m0, n0,
                     AddBiasRound{lb});
        } else {
            float* sC = (float*)sm;
            int lane = tid & 31, g = lane >> 2, t4 = lane & 3;
            int warp = tid >> 5, wm = warp & 1, wn = warp >> 1;
            float* zb = g_z + (size_t)z * HW_ * C_;
            int zoff = n0 - C_;
            __syncthreads();
            #pragma unroll
            for (int j = 0; j < 2; j++) {
                if (wm == j) {
                    #pragma unroll
                    for (int mf = 0; mf < 4; mf++) {
                        int rl = mf * 16 + g;
                        #pragma unroll
                        for (int nf = 0; nf < 8; nf++) {
                            int cc = wn * 64 + nf * 8 + 2 * t4;
                            *(float2*)(sC + rl * 132 + cc) =
                                make_float2(acc[mf][nf][0], acc[mf][nf][1]);
                            *(float2*)(sC + (rl + 8) * 132 + cc) =
                                make_float2(acc[mf][nf][2], acc[mf][nf][3]);
                        }
                    }
                }
                __syncthreads();
                for (int i = tid; i < 2048; i += 128) {
                    int row = i >> 5, q = i & 31;
                    float4 v = *(float4*)(sC + row * 132 + 4 * q);
                    float4 bb = *(const float4*)(lb + C_ + zoff + 4 * q);
                    v.x += bb.x; v.y += bb.y; v.z += bb.z; v.w += bb.w;
                    *(float4*)(zb + (size_t)(m0 + 64 * j + row) * C_ + zoff + 4 * q) = v;
                }
                __syncthreads();
            }
        }
    } else {
        // ---- gate GEMM (only 3 n-tiles) ----
        if (blockIdx.y >= 3) return;
        gemm_core<1>(g_feR, C_, g_twR, m0, n0, tid, sm, acc);
        float c0 = cp[0];
        float s1 = (1.0f + 0.5f * ap[0]) / c0;
        epi_nchw(sm, acc, tid, g_gate, HW_, m0, n0, GateXform{tb, c0, s1});
    }
}

// ---------------------------------------------------------------------------
// out GEMM: out[d][m] = sum_c y[m][c]*out_w[d][c] + out_b[d]
// ---------------------------------------------------------------------------
__global__ void __launch_bounds__(128, 2) k_out_mma(const float* __restrict__ ob,
                                                    float* __restrict__ out) {
    extern __shared__ __align__(16) uint32_t sm[];
    int tid = threadIdx.x;
    int b = blockIdx.z, m0 = blockIdx.x * 128, n0 = blockIdx.y * 128;
    float acc[4][8][4];
    #pragma unroll
    for (int i = 0; i < 4; i++)
        #pragma unroll
        for (int j = 0; j < 8; j++)
            #pragma unroll
            for (int k = 0; k < 4; k++) acc[i][j][k] = 0.0f;

    gemm_core<1>(g_buf1 + (size_t)b * HW_ * C_, C_, g_owR, m0, n0, tid, sm, acc);

    epi_nchw(sm, acc, tid, out + (size_t)b * C_ * HW_, HW_, m0, n0, AddBias{ob});
}

// ===========================================================================
// Fused DCT -> gate -> iDCT per (b,c) image, tf32 mma (one image per block,
// 58 KB smem, 8 warps, warp tile 16x32). Gate prefetched into registers
// before tile staging.
// ---------------------------------------------------------------------------
#define DS 76
#define DTILE (64 * DS)
#define DCT_SMEM_BYTES (3 * DTILE * 4)

__device__ __forceinline__ void dct_mm(const uint32_t* __restrict__ pA,
                                       const uint32_t* __restrict__ pB,
                                       float acc[4][4], int r, int nb,
                                       int g, int t4) {
    #pragma unroll
    for (int nf = 0; nf < 4; nf++)
        #pragma unroll
        for (int j = 0; j < 4; j++) acc[nf][j] = 0.0f;
    #pragma unroll
    for (int k8 = 0; k8 < 8; k8++) {
        uint32_t a0 = pA[r * DS + k8 * 8 + t4];
        uint32_t a1 = pA[(r + 8) * DS + k8 * 8 + t4];
        uint32_t a2 = pA[r * DS + k8 * 8 + t4 + 4];
        uint32_t a3 = pA[(r + 8) * DS + k8 * 8 + t4 + 4];
        #pragma unroll
        for (int nf = 0; nf < 4; nf++) {
            int n = nb + nf * 8 + g;
            uint32_t b0 = pB[(k8 * 8 + t4) * DS + n];
            uint32_t b1 = pB[(k8 * 8 + t4 + 4) * DS + n];
            mma8(acc[nf], a0, a1, a2, a3, b0, b1);
        }
    }
}

__global__ void __launch_bounds__(256, 3) k_dct_mma() {
    extern __shared__ uint32_t dsm[];
    uint32_t* tW = dsm;
    uint32_t* tA = dsm + DTILE;
    uint32_t* tB = dsm + 2 * DTILE;
    int bc = blockIdx.x;
    int c = bc % C_;
    int tid = threadIdx.x;
    int lane = tid & 31, g = lane >> 2, t4 = lane & 3;
    int warp = tid >> 5, wm = warp & 3, wn = warp >> 2;
    int r = wm * 16 + g, nb = wn * 32;

    // Prefetch gate values (used after mm2) before tile staging.
    float gv[4][4];
    {
        const float* gp = g_gate + (size_t)c * HW_;
        #pragma unroll
        for (int nf = 0; nf < 4; nf++) {
            int cc = nb + nf * 8 + 2 * t4;
            gv[nf][0] = gp[cc * 64 + r];
            gv[nf][1] = gp[(cc + 1) * 64 + r];
            gv[nf][2] = gp[cc * 64 + r + 8];
            gv[nf][3] = gp[(cc + 1) * 64 + r + 8];
        }
    }

    const uint4* xim4 = (const uint4*)(g_buf1 + (size_t)bc * HW_);
    const uint4* w4p = (const uint4*)g_W;
    #pragma unroll
    for (int i = tid; i < 1024; i += 256) {
        int h = i >> 4, w4 = (i & 15) * 4;
        *(uint4*)(tW + h * DS + w4) = w4p[i];
        *(uint4*)(tA + h * DS + w4) = xim4[i];
    }
    __syncthreads();

    float acc[4][4];

    // mm1 -> tB transposed [w][n]
    dct_mm(tW, tA, acc, r, nb, g, t4);
    #pragma unroll
    for (int nf = 0; nf < 4; nf++) {
        int cc = nb + nf * 8 + 2 * t4;
        tB[cc * DS + r]           = f2tf(acc[nf][0]);
        tB[(cc + 1) * DS + r]     = f2tf(acc[nf][1]);
        tB[cc * DS + r + 8]       = f2tf(acc[nf][2]);
        tB[(cc + 1) * DS + r + 8] = f2tf(acc[nf][3]);
    }
    __syncthreads();

    // mm2 + gate -> tA [k][n]
    dct_mm(tW, tB, acc, r, nb, g, t4);
    #pragma unroll
    for (int nf = 0; nf < 4; nf++) {
        int cc = nb + nf * 8 + 2 * t4;
        tA[r * DS + cc]           = f2tf(acc[nf][0] * gv[nf][0]);
        tA[r * DS + cc + 1]       = f2tf(acc[nf][1] * gv[nf][1]);
        tA[(r + 8) * DS + cc]     = f2tf(acc[nf][2] * gv[nf][2]);
        tA[(r + 8) * DS + cc + 1] = f2tf(acc[nf][3] * gv[nf][3]);
    }
    __syncthreads();

    // mm3 -> tB transposed [h][k]
    dct_mm(tA, tW, acc, r, nb, g, t4);
    #pragma unroll
    for (int nf = 0; nf < 4; nf++) {
        int cc = nb + nf * 8 + 2 * t4;
        tB[cc * DS + r]           = f2tf(acc[nf][0]);
        tB[(cc + 1) * DS + r]     = f2tf(acc[nf][1]);
        tB[cc * DS + r + 8]       = f2tf(acc[nf][2]);
        tB[(cc + 1) * DS + r + 8] = f2tf(acc[nf][3]);
    }
    __syncthreads();

    // mm4 -> gmem
    dct_mm(tB, tW, acc, r, nb, g, t4);
    float* xo = g_buf0 + (size_t)bc * HW_;
    #pragma unroll
    for (int nf = 0; nf < 4; nf++) {
        int cc = nb + nf * 8 + 2 * t4;
        *(float2*)(xo + r * 64 + cc)       = make_float2(acc[nf][0], acc[nf][1]);
        *(float2*)(xo + (r + 8) * 64 + cc) = make_float2(acc[nf][2], acc[nf][3]);
    }
}

// ---------------------------------------------------------------------------
// LayerNorm over channels + SiLU(z) gate. 32 tokens per block of 256 threads.
// Output y tf32-pre-rounded (consumed only by out GEMM).
// ---------------------------------------------------------------------------
#define LNS 34
#define LN_SMEM_BYTES (C_ * LNS * 4)   // 52224

__global__ void __launch_bounds__(256) k_ln(const float* __restrict__ lng,
                                            const float* __restrict__ lnb) {
    extern __shared__ float s[];
    int tid = threadIdx.x;
    int mglob = blockIdx.x * 32;
    int b = mglob >> 12;
    int mloc = mglob & 4095;
    const float* xi = g_buf0 + (size_t)b * C_ * HW_ + mloc;
    #pragma unroll
    for (int i = tid; i < C_ * 32; i += 256) {
        int cc = i >> 5, t = i & 31;
        s[cc * LNS + t] = xi[(size_t)cc * HW_ + t];
    }
    __syncthreads();
    int tk = tid >> 3, g = tid & 7;
    float sum = 0.0f, ss = 0.0f;
    #pragma unroll 8
    for (int ii = 0; ii < 48; ii++) {
        int cc = g + ii * 8;
        float v = s[cc * LNS + tk];
        sum += v; ss += v * v;
    }
    #pragma unroll
    for (int off = 4; off; off >>= 1) {
        sum += __shfl_down_sync(0xffffffffu, sum, off);
        ss  += __shfl_down_sync(0xffffffffu, ss,  off);
    }
    int lane = tid & 31;
    int src = lane & ~7;
    sum = __shfl_sync(0xffffffffu, sum, src);
    ss  = __shfl_sync(0xffffffffu, ss,  src);
    float mu = sum * (1.0f / 384.0f);
    float var = ss * (1.0f / 384.0f) - mu * mu;
    float rstd = rsqrtf(fmaxf(var, 0.0f) + 1e-5f);

    int mt = mloc + tk;
    const float* zp = g_z + ((size_t)b * HW_ + mt) * C_;
    float* yp = g_buf1 + ((size_t)b * HW_ + mt) * C_;
    #pragma unroll 4
    for (int ii = 0; ii < 12; ii++) {
        int c0 = g * 48 + ii * 4;
        float4 zv = *(const float4*)(zp + c0);
        float4 gg = *(const float4*)(lng + c0);
        float4 bb = *(const float4*)(lnb + c0);
        float y0 = (s[(c0 + 0) * LNS + tk] - mu) * rstd * gg.x + bb.x;
        float y1 = (s[(c0 + 1) * LNS + tk] - mu) * rstd * gg.y + bb.y;
        float y2 = (s[(c0 + 2) * LNS + tk] - mu) * rstd * gg.z + bb.z;
        float y3 = (s[(c0 + 3) * LNS + tk] - mu) * rstd * gg.w + bb.w;
        y0 *= zv.x / (1.0f + __expf(-zv.x));
        y1 *= zv.y / (1.0f + __expf(-zv.y));
        y2 *= zv.z / (1.0f + __expf(-zv.z));
        y3 *= zv.w / (1.0f + __expf(-zv.w));
        *(float4*)(yp + c0) = make_float4(f2tf_f(y0), f2tf_f(y1),
                                          f2tf_f(y2), f2tf_f(y3));
    }
}

// ---------------------------------------------------------------------------
extern "C" void kernel_launch(void* const* d_in, const int* in_sizes, int n_in,
                              void* d_out, int out_size) {
    const float* x     = (const float*)d_in[0];
    const float* fe    = (const float*)d_in[1];
    const float* dw_w  = (const float*)d_in[2];
    const float* dw_b  = (const float*)d_in[3];
    const float* lin_w = (const float*)d_in[4];
    const float* lin_b = (const float*)d_in[5];
    const float* tok_w = (const float*)d_in[6];
    const float* tok_b = (const float*)d_in[7];
    const float* cc    = (const float*)d_in[8];
    const float* alpha = (const float*)d_in[9];
    const float* ln_g  = (const float*)d_in[10];
    const float* ln_b  = (const float*)d_in[11];
    const float* out_w = (const float*)d_in[12];
    const float* out_b = (const float*)d_in[13];
    float* out = (float*)d_out;

    cudaFuncSetAttribute(k_dct_mma, cudaFuncAttributeMaxDynamicSharedMemorySize,
                         DCT_SMEM_BYTES);
    cudaFuncSetAttribute(k_lingate_mma, cudaFuncAttributeMaxDynamicSharedMemorySize,
                         GEMM_SMEM_BYTES);
    cudaFuncSetAttribute(k_out_mma, cudaFuncAttributeMaxDynamicSharedMemorySize,
                         GEMM_SMEM_BYTES);
    cudaFuncSetAttribute(k_ln, cudaFuncAttributeMaxDynamicSharedMemorySize,
                         LN_SMEM_BYTES);

    k_prep<<<PREP_GRID, 256>>>(x, dw_w, dw_b, fe, lin_w, tok_w, out_w);
    k_lingate_mma<<<dim3(32, 6, 9), 128, GEMM_SMEM_BYTES>>>(lin_b, tok_b, cc, alpha);
    k_dct_mma<<<B_ * C_, 256, DCT_SMEM_BYTES>>>();
    k_ln<<<(B_ * HW_) / 32, 256, LN_SMEM_BYTES>>>(ln_g, ln_b);
    k_out_mma<<<dim3(32, 3, B_), 128, GEMM_SMEM_BYTES>>>(out_b, out);
}